// round 6
// baseline (speedup 1.0000x reference)
#include <cuda_runtime.h>
#include <math.h>

#define BB   4
#define SS   64
#define DDIM 512
#define HH   8
#define DH   64
#define DFF  2048
#define LLAY 2
#define VV   32128
#define TT   16
#define NEGV (-1e9f)

#define GF_RES  1
#define GF_RELU 2

// ---------------- scratch (device globals; no allocations) ----------------
__device__ float g_x  [BB*SS*DDIM];     // encoder stream
__device__ float g_h  [BB*SS*DDIM];     // rmsnorm out
__device__ float g_q  [BB*SS*DDIM];
__device__ float g_k  [BB*SS*DDIM];
__device__ float g_v  [BB*SS*DDIM];
__device__ float g_at [BB*SS*DDIM];
__device__ float g_ff [BB*SS*DFF];
__device__ float g_hs [BB*SS*DDIM];     // encoder output
__device__ float g_ckc[LLAY*BB*SS*DDIM];  // cross K cache
__device__ float g_cvc[LLAY*BB*SS*DDIM];  // cross V cache
__device__ float g_skc[LLAY*BB*TT*DDIM];  // self K cache
__device__ float g_svc[LLAY*BB*TT*DDIM];  // self V cache
__device__ float g_xd [BB*DDIM];        // decoder token stream
__device__ float g_qd [BB*DDIM];
__device__ float g_ad [BB*DDIM];
__device__ float g_fd [BB*DFF];
__device__ float g_logits[BB*VV];

// ---------------- embedding lookup ----------------
__global__ void embed_kernel(const int* __restrict__ ids, const float* __restrict__ emb) {
    int row = blockIdx.x;          // b*S + s
    int id  = ids[row];
    for (int d = threadIdx.x; d < DDIM; d += 256)
        g_x[row*DDIM + d] = emb[(size_t)id*DDIM + d];
}

// ---------------- rmsnorm over D=512 rows ----------------
__global__ void rmsnorm_kernel(const float* __restrict__ x, const float* __restrict__ w,
                               float* __restrict__ o) {
    int r = blockIdx.x, tid = threadIdx.x;  // 256 threads
    __shared__ float red[256];
    float a = x[r*DDIM + tid];
    float b = x[r*DDIM + 256 + tid];
    red[tid] = a*a + b*b;
    __syncthreads();
    for (int s = 128; s > 0; s >>= 1) { if (tid < s) red[tid] += red[tid+s]; __syncthreads(); }
    float inv = rsqrtf(red[0] / (float)DDIM + 1e-6f);
    o[r*DDIM + tid]       = a * inv * w[tid];
    o[r*DDIM + 256 + tid] = b * inv * w[256 + tid];
}

// ---------------- tiled SGEMM: C = op(A[M,K] @ W[K,N]) ----------------
__global__ void gemm_tiled(const float* __restrict__ A, const float* __restrict__ W,
                           const float* __restrict__ res, float* __restrict__ C,
                           int M, int N, int K, int flags) {
    __shared__ float As[16][64];
    __shared__ float Bs[16][64];
    int row0 = blockIdx.y * 64, col0 = blockIdx.x * 64;
    int tid = threadIdx.x;
    int ty = tid / 16, tx = tid % 16;
    float acc[4][4];
    #pragma unroll
    for (int i = 0; i < 4; i++)
        #pragma unroll
        for (int j = 0; j < 4; j++) acc[i][j] = 0.f;

    for (int k0 = 0; k0 < K; k0 += 16) {
        #pragma unroll
        for (int p = 0; p < 4; p++) {
            int i = tid + p*256;
            int r = i >> 4, c = i & 15;
            As[c][r] = A[(row0 + r)*K + k0 + c];
        }
        #pragma unroll
        for (int p = 0; p < 4; p++) {
            int i = tid + p*256;
            int r = i >> 6, c = i & 63;
            Bs[r][c] = W[(size_t)(k0 + r)*N + col0 + c];
        }
        __syncthreads();
        #pragma unroll
        for (int k = 0; k < 16; k++) {
            float a[4], b[4];
            #pragma unroll
            for (int i = 0; i < 4; i++) a[i] = As[k][ty*4 + i];
            #pragma unroll
            for (int j = 0; j < 4; j++) b[j] = Bs[k][tx*4 + j];
            #pragma unroll
            for (int i = 0; i < 4; i++)
                #pragma unroll
                for (int j = 0; j < 4; j++) acc[i][j] += a[i]*b[j];
        }
        __syncthreads();
    }
    #pragma unroll
    for (int i = 0; i < 4; i++) {
        int r = row0 + ty*4 + i;
        #pragma unroll
        for (int j = 0; j < 4; j++) {
            int c = col0 + tx*4 + j;
            float v = acc[i][j];
            if (flags & GF_RES)  v += res[(size_t)r*N + c];
            if (flags & GF_RELU) v = fmaxf(v, 0.f);
            C[(size_t)r*N + c] = v;
        }
    }
}

// ---------------- encoder attention: one block per (b,h) ----------------
__global__ void enc_attn(const float* __restrict__ Q, const float* __restrict__ K,
                         const float* __restrict__ V, const float* __restrict__ mask,
                         float* __restrict__ O) {
    int bh = blockIdx.x; int b = bh >> 3, h = bh & 7;
    int tid = threadIdx.x;  // 64 threads
    __shared__ float Ks[64*65], Vs[64*65], sc[64], se[64];
    for (int i = tid; i < 4096; i += 64) {
        int r = i >> 6, c = i & 63;
        Ks[r*65 + c] = K[(size_t)(b*SS + r)*DDIM + h*DH + c];
        Vs[r*65 + c] = V[(size_t)(b*SS + r)*DDIM + h*DH + c];
    }
    __syncthreads();
    float bias = (1.f - mask[b*SS + tid]) * NEGV;
    for (int q = 0; q < SS; q++) {
        const float* qr = &Q[(size_t)(b*SS + q)*DDIM + h*DH];
        float s = 0.f;
        #pragma unroll 8
        for (int d = 0; d < DH; d++) s += qr[d]*Ks[tid*65 + d];
        sc[tid] = s * 0.125f + bias;
        __syncthreads();
        float mx = -1e30f;
        for (int j = 0; j < 64; j++) mx = fmaxf(mx, sc[j]);
        se[tid] = expf(sc[tid] - mx);
        __syncthreads();
        float den = 0.f;
        for (int j = 0; j < 64; j++) den += se[j];
        float o = 0.f;
        #pragma unroll 8
        for (int j = 0; j < 64; j++) o += se[j]*Vs[j*65 + tid];
        O[(size_t)(b*SS + q)*DDIM + h*DH + tid] = o / den;
        __syncthreads();
    }
}

// ---------------- decoder tiny GEMM (4 rows): out[4,N] = epi(rms?(x) @ W) ----------------
__global__ void gemv4(const float* __restrict__ x, int K,
                      const float* __restrict__ ln,
                      const float* __restrict__ W, int N,
                      const float* __restrict__ res, float* __restrict__ out, int relu) {
    __shared__ float xs[4*DFF];
    __shared__ float ssq[4], sinv[4];
    __shared__ float pb[4][4][64];
    int tid = threadIdx.x;  // 256
    if (tid < 4) ssq[tid] = 0.f;
    __syncthreads();
    float lsq[4] = {0.f,0.f,0.f,0.f};
    for (int i = tid; i < 4*K; i += 256) {
        int m = i / K, k = i - m*K;
        float v = x[m*K + k];
        lsq[m] += v*v;
        xs[i] = ln ? v*ln[k] : v;
    }
    if (ln) { for (int m = 0; m < 4; m++) atomicAdd(&ssq[m], lsq[m]); }
    __syncthreads();
    if (ln && tid < 4) sinv[tid] = rsqrtf(ssq[tid] / (float)K + 1e-6f);
    __syncthreads();
    int col = blockIdx.x*64 + (tid & 63);
    int kg = tid >> 6;
    int kc = K >> 2;
    float a0 = 0.f, a1 = 0.f, a2 = 0.f, a3 = 0.f;
    int ke = kg*kc + kc;
    #pragma unroll 4
    for (int k = kg*kc; k < ke; k++) {
        float w = W[(size_t)k*N + col];
        a0 += xs[k]*w; a1 += xs[K + k]*w; a2 += xs[2*K + k]*w; a3 += xs[3*K + k]*w;
    }
    pb[kg][0][tid & 63] = a0; pb[kg][1][tid & 63] = a1;
    pb[kg][2][tid & 63] = a2; pb[kg][3][tid & 63] = a3;
    __syncthreads();
    if (kg == 0) {
        int c = tid & 63;
        for (int m = 0; m < 4; m++) {
            float s = pb[0][m][c] + pb[1][m][c] + pb[2][m][c] + pb[3][m][c];
            if (ln) s *= sinv[m];
            if (res) s += res[m*N + col];
            if (relu) s = fmaxf(s, 0.f);
            out[m*N + col] = s;
        }
    }
}

// ---------------- fused rmsnorm + QKV (decoder, 1 token) ----------------
__global__ void gemv4_qkv(const float* __restrict__ x, const float* __restrict__ ln,
                          const float* __restrict__ wq, const float* __restrict__ wk,
                          const float* __restrict__ wv,
                          float* __restrict__ qout, float* __restrict__ kdst,
                          float* __restrict__ vdst) {
    __shared__ float xs[4*DDIM];
    __shared__ float ssq[4], sinv[4];
    __shared__ float pb[4][4][64];
    int tid = threadIdx.x;  // 256
    if (tid < 4) ssq[tid] = 0.f;
    __syncthreads();
    float lsq[4] = {0.f,0.f,0.f,0.f};
    for (int i = tid; i < 4*DDIM; i += 256) {
        int m = i >> 9, k = i & 511;
        float v = x[m*DDIM + k];
        lsq[m] += v*v;
        xs[i] = v*ln[k];
    }
    for (int m = 0; m < 4; m++) atomicAdd(&ssq[m], lsq[m]);
    __syncthreads();
    if (tid < 4) sinv[tid] = rsqrtf(ssq[tid] / (float)DDIM + 1e-6f);
    __syncthreads();
    int gcol = blockIdx.x*64 + (tid & 63);          // 0..1535
    int seg = gcol >> 9;
    int col = gcol & 511;
    const float* W = (seg == 0) ? wq : (seg == 1 ? wk : wv);
    int kg = tid >> 6;
    float a0 = 0.f, a1 = 0.f, a2 = 0.f, a3 = 0.f;
    int ke = kg*128 + 128;
    #pragma unroll 4
    for (int k = kg*128; k < ke; k++) {
        float w = W[k*DDIM + col];
        a0 += xs[k]*w; a1 += xs[DDIM + k]*w; a2 += xs[2*DDIM + k]*w; a3 += xs[3*DDIM + k]*w;
    }
    pb[kg][0][tid & 63] = a0; pb[kg][1][tid & 63] = a1;
    pb[kg][2][tid & 63] = a2; pb[kg][3][tid & 63] = a3;
    __syncthreads();
    if (kg == 0) {
        int c = tid & 63;
        for (int m = 0; m < 4; m++) {
            float s = (pb[0][m][c] + pb[1][m][c] + pb[2][m][c] + pb[3][m][c]) * sinv[m];
            if (seg == 0)      qout[m*DDIM + col] = s;
            else if (seg == 1) kdst[m*TT*DDIM + col] = s;
            else               vdst[m*TT*DDIM + col] = s;
        }
    }
}

// ---------------- decoder self-attention (incremental) ----------------
__global__ void dec_self_attn(int l, int nk) {
    int bh = blockIdx.x; int b = bh >> 3, h = bh & 7;
    int tid = threadIdx.x;  // 64
    __shared__ float sc[TT], se[TT];
    const float* q = &g_qd[b*DDIM + h*DH];
    if (tid < nk) {
        const float* kr = &g_skc[(size_t)((l*BB + b)*TT + tid)*DDIM + h*DH];
        float s = 0.f;
        #pragma unroll 8
        for (int d = 0; d < DH; d++) s += q[d]*kr[d];
        sc[tid] = s * 0.125f;
    }
    __syncthreads();
    float mx = -1e30f;
    for (int j = 0; j < nk; j++) mx = fmaxf(mx, sc[j]);
    if (tid < nk) se[tid] = expf(sc[tid] - mx);
    __syncthreads();
    float den = 0.f;
    for (int j = 0; j < nk; j++) den += se[j];
    float o = 0.f;
    for (int j = 0; j < nk; j++)
        o += se[j]*g_svc[(size_t)((l*BB + b)*TT + j)*DDIM + h*DH + tid];
    g_ad[b*DDIM + h*DH + tid] = o / den;
}

// ---------------- decoder cross-attention (1 token x 64 enc keys) ----------------
__global__ void dec_cross_attn(int l, const float* __restrict__ mask) {
    int bh = blockIdx.x; int b = bh >> 3, h = bh & 7;
    int tid = threadIdx.x;  // 64
    __shared__ float sc[64], se[64];
    const float* q = &g_qd[b*DDIM + h*DH];
    const float* kr = &g_ckc[(size_t)((l*BB + b)*SS + tid)*DDIM + h*DH];
    float s = 0.f;
    #pragma unroll 8
    for (int d = 0; d < DH; d++) s += q[d]*kr[d];
    sc[tid] = s * 0.125f + (1.f - mask[b*SS + tid]) * NEGV;
    __syncthreads();
    float mx = -1e30f;
    for (int j = 0; j < 64; j++) mx = fmaxf(mx, sc[j]);
    se[tid] = expf(sc[tid] - mx);
    __syncthreads();
    float den = 0.f;
    for (int j = 0; j < 64; j++) den += se[j];
    float o = 0.f;
    #pragma unroll 8
    for (int j = 0; j < 64; j++)
        o += se[j]*g_cvc[(size_t)((l*BB + b)*SS + j)*DDIM + h*DH + tid];
    g_ad[b*DDIM + h*DH + tid] = o / den;
}

// ---------------- logits: rms(x_dec, lnf) @ lm_head -> g_logits ----------------
__global__ void logits_kernel(const float* __restrict__ lnf, const float* __restrict__ lm) {
    __shared__ float xs[4*DDIM];
    __shared__ float ssq[4], sinv[4];
    __shared__ float pb[2][4][128];
    int tid = threadIdx.x;  // 256
    if (tid < 4) ssq[tid] = 0.f;
    __syncthreads();
    float lsq[4] = {0.f,0.f,0.f,0.f};
    for (int i = tid; i < 4*DDIM; i += 256) {
        int m = i >> 9, k = i & 511;
        float v = g_xd[i];
        lsq[m] += v*v;
        xs[i] = v*lnf[k];
    }
    for (int m = 0; m < 4; m++) atomicAdd(&ssq[m], lsq[m]);
    __syncthreads();
    if (tid < 4) sinv[tid] = rsqrtf(ssq[tid] / (float)DDIM + 1e-6f);
    __syncthreads();
    int col = blockIdx.x*128 + (tid & 127);
    int kg = tid >> 7;  // 0..1
    float a0 = 0.f, a1 = 0.f, a2 = 0.f, a3 = 0.f;
    int ke = kg*256 + 256;
    #pragma unroll 4
    for (int k = kg*256; k < ke; k++) {
        float w = lm[(size_t)k*VV + col];
        a0 += xs[k]*w; a1 += xs[DDIM + k]*w; a2 += xs[2*DDIM + k]*w; a3 += xs[3*DDIM + k]*w;
    }
    pb[kg][0][tid & 127] = a0; pb[kg][1][tid & 127] = a1;
    pb[kg][2][tid & 127] = a2; pb[kg][3][tid & 127] = a3;
    __syncthreads();
    if (kg == 0) {
        int c = tid & 127;
        for (int m = 0; m < 4; m++)
            g_logits[(size_t)m*VV + col] = sinv[m]*(pb[0][m][c] + pb[1][m][c]);
    }
}

// ---------------- softmax + argmax + write probs/pred + zero x_dec ----------------
__global__ void softmax_kernel(float* __restrict__ out, int iter) {
    int b = blockIdx.x, tid = threadIdx.x;  // 512
    __shared__ float smx[512]; __shared__ int sidx[512]; __shared__ float ssum[512];
    float mx = -1e30f; int mi = 0;
    for (int v = tid; v < VV; v += 512) {
        float f = g_logits[(size_t)b*VV + v];
        if (f > mx) { mx = f; mi = v; }
    }
    smx[tid] = mx; sidx[tid] = mi;
    __syncthreads();
    for (int s = 256; s > 0; s >>= 1) {
        if (tid < s) {
            float o = smx[tid + s];
            if (o > smx[tid] || (o == smx[tid] && sidx[tid + s] < sidx[tid])) {
                smx[tid] = o; sidx[tid] = sidx[tid + s];
            }
        }
        __syncthreads();
    }
    float M = smx[0];
    float sum = 0.f;
    for (int v = tid; v < VV; v += 512) sum += expf(g_logits[(size_t)b*VV + v] - M);
    ssum[tid] = sum;
    __syncthreads();
    for (int s = 256; s > 0; s >>= 1) { if (tid < s) ssum[tid] += ssum[tid + s]; __syncthreads(); }
    float inv = 1.f / ssum[0];
    float* pr = &out[(size_t)(b*TT + iter)*VV];
    for (int v = tid; v < VV; v += 512)
        pr[v] = expf(g_logits[(size_t)b*VV + v] - M) * inv;
    if (tid == 0)
        out[(size_t)BB*TT*VV + b*TT + iter] = (sidx[0] == 0) ? 1.0f : 0.0f;
    g_xd[b*DDIM + tid] = 0.f;  // prepare next-token accumulator
}

// ---------------- soft embedding: x_dec += probs @ emb ----------------
__global__ void yemb_kernel(const float* __restrict__ emb, const float* __restrict__ out, int iter) {
    __shared__ float ps[4][128];
    int tid = threadIdx.x;  // 512
    int vb = blockIdx.x*128;
    {
        int m = tid >> 7, j = tid & 127;
        ps[m][j] = out[(size_t)(m*TT + iter)*VV + vb + j];
    }
    __syncthreads();
    float a0 = 0.f, a1 = 0.f, a2 = 0.f, a3 = 0.f;
    #pragma unroll 4
    for (int j = 0; j < 128; j++) {
        float e = emb[(size_t)(vb + j)*DDIM + tid];
        a0 += ps[0][j]*e; a1 += ps[1][j]*e; a2 += ps[2][j]*e; a3 += ps[3][j]*e;
    }
    atomicAdd(&g_xd[0*DDIM + tid], a0);
    atomicAdd(&g_xd[1*DDIM + tid], a1);
    atomicAdd(&g_xd[2*DDIM + tid], a2);
    atomicAdd(&g_xd[3*DDIM + tid], a3);
}

// ---------------- first decoder token = emb[PAD_ID=0] ----------------
__global__ void init_y(const float* __restrict__ emb) {
    int tid = threadIdx.x;  // 512
    float e = emb[tid];
    for (int m = 0; m < 4; m++) g_xd[m*DDIM + tid] = e;
}

// ---------------- launcher ----------------
extern "C" void kernel_launch(void* const* d_in, const int* in_sizes, int n_in,
                              void* d_out, int out_size) {
    const int*   ids     = (const int*)  d_in[0];
    const float* mask    = (const float*)d_in[1];
    const float* emb     = (const float*)d_in[2];
    const float* enc_wq  = (const float*)d_in[3];
    const float* enc_wk  = (const float*)d_in[4];
    const float* enc_wv  = (const float*)d_in[5];
    const float* enc_wo  = (const float*)d_in[6];
    const float* enc_ln1 = (const float*)d_in[7];
    const float* enc_w1  = (const float*)d_in[8];
    const float* enc_w2  = (const float*)d_in[9];
    const float* enc_ln2 = (const float*)d_in[10];
    const float* enc_lnf = (const float*)d_in[11];
    const float* dec_sq  = (const float*)d_in[12];
    const float* dec_sk  = (const float*)d_in[13];
    const float* dec_sv  = (const float*)d_in[14];
    const float* dec_so  = (const float*)d_in[15];
    const float* dec_ln1 = (const float*)d_in[16];
    const float* dec_cq  = (const float*)d_in[17];
    const float* dec_ck  = (const float*)d_in[18];
    const float* dec_cv  = (const float*)d_in[19];
    const float* dec_co  = (const float*)d_in[20];
    const float* dec_ln2 = (const float*)d_in[21];
    const float* dec_w1  = (const float*)d_in[22];
    const float* dec_w2  = (const float*)d_in[23];
    const float* dec_ln3 = (const float*)d_in[24];
    const float* dec_lnf = (const float*)d_in[25];
    const float* lm      = (const float*)d_in[26];
    float* out = (float*)d_out;

    float *gx, *gh, *gq, *gk, *gv, *gat, *gff, *ghs, *gckc, *gcvc;
    float *gxd, *gqd, *gad, *gfd, *gskc, *gsvc;
    cudaGetSymbolAddress((void**)&gx,   g_x);
    cudaGetSymbolAddress((void**)&gh,   g_h);
    cudaGetSymbolAddress((void**)&gq,   g_q);
    cudaGetSymbolAddress((void**)&gk,   g_k);
    cudaGetSymbolAddress((void**)&gv,   g_v);
    cudaGetSymbolAddress((void**)&gat,  g_at);
    cudaGetSymbolAddress((void**)&gff,  g_ff);
    cudaGetSymbolAddress((void**)&ghs,  g_hs);
    cudaGetSymbolAddress((void**)&gckc, g_ckc);
    cudaGetSymbolAddress((void**)&gcvc, g_cvc);
    cudaGetSymbolAddress((void**)&gxd,  g_xd);
    cudaGetSymbolAddress((void**)&gqd,  g_qd);
    cudaGetSymbolAddress((void**)&gad,  g_ad);
    cudaGetSymbolAddress((void**)&gfd,  g_fd);
    cudaGetSymbolAddress((void**)&gskc, g_skc);
    cudaGetSymbolAddress((void**)&gsvc, g_svc);

    const int MROWS = BB*SS;                   // 256
    const size_t DD2 = (size_t)DDIM*DDIM;      // 262144
    const size_t DF  = (size_t)DDIM*DFF;       // 1048576

    // ===== encoder =====
    embed_kernel<<<MROWS, 256>>>(ids, emb);
    for (int l = 0; l < LLAY; l++) {
        rmsnorm_kernel<<<MROWS, 256>>>(gx, enc_ln1 + l*DDIM, gh);
        dim3 g8(8, 4), g32(32, 4);
        gemm_tiled<<<g8, 256>>>(gh, enc_wq + l*DD2, nullptr, gq, MROWS, DDIM, DDIM, 0);
        gemm_tiled<<<g8, 256>>>(gh, enc_wk + l*DD2, nullptr, gk, MROWS, DDIM, DDIM, 0);
        gemm_tiled<<<g8, 256>>>(gh, enc_wv + l*DD2, nullptr, gv, MROWS, DDIM, DDIM, 0);
        enc_attn<<<BB*HH, 64>>>(gq, gk, gv, mask, gat);
        gemm_tiled<<<g8, 256>>>(gat, enc_wo + l*DD2, gx, gx, MROWS, DDIM, DDIM, GF_RES);
        rmsnorm_kernel<<<MROWS, 256>>>(gx, enc_ln2 + l*DDIM, gh);
        gemm_tiled<<<g32, 256>>>(gh, enc_w1 + l*DF, nullptr, gff, MROWS, DFF, DDIM, GF_RELU);
        gemm_tiled<<<g8, 256>>>(gff, enc_w2 + l*DF, gx, gx, MROWS, DDIM, DFF, GF_RES);
    }
    rmsnorm_kernel<<<MROWS, 256>>>(gx, enc_lnf, ghs);

    // cross K/V precompute (hs is fixed across decode iterations)
    for (int l = 0; l < LLAY; l++) {
        dim3 g8(8, 4);
        gemm_tiled<<<g8, 256>>>(ghs, dec_ck + l*DD2, nullptr, gckc + (size_t)l*MROWS*DDIM,
                                MROWS, DDIM, DDIM, 0);
        gemm_tiled<<<g8, 256>>>(ghs, dec_cv + l*DD2, nullptr, gcvc + (size_t)l*MROWS*DDIM,
                                MROWS, DDIM, DDIM, 0);
    }

    // ===== incremental decoder (KV-cached; numerically identical to full re-run) =====
    init_y<<<1, 512>>>(emb);
    for (int t = 0; t < TT; t++) {
        for (int l = 0; l < LLAY; l++) {
            gemv4_qkv<<<24, 256>>>(gxd, dec_ln1 + l*DDIM,
                                   dec_sq + l*DD2, dec_sk + l*DD2, dec_sv + l*DD2,
                                   gqd,
                                   gskc + (size_t)(l*BB*TT + t)*DDIM,
                                   gsvc + (size_t)(l*BB*TT + t)*DDIM);
            dec_self_attn<<<BB*HH, 64>>>(l, t + 1);
            gemv4<<<8, 256>>>(gad, DDIM, nullptr, dec_so + l*DD2, DDIM, gxd, gxd, 0);
            gemv4<<<8, 256>>>(gxd, DDIM, dec_ln2 + l*DDIM, dec_cq + l*DD2, DDIM, nullptr, gqd, 0);
            dec_cross_attn<<<BB*HH, 64>>>(l, mask);
            gemv4<<<8, 256>>>(gad, DDIM, nullptr, dec_co + l*DD2, DDIM, gxd, gxd, 0);
            gemv4<<<32, 256>>>(gxd, DDIM, dec_ln3 + l*DDIM, dec_w1 + l*DF, DFF, nullptr, gfd, 1);
            gemv4<<<8, 256>>>(gfd, DFF, nullptr, dec_w2 + l*DF, DDIM, gxd, gxd, 0);
        }
        logits_kernel<<<251, 256>>>(dec_lnf, lm);
        softmax_kernel<<<BB, 512>>>(out, t);
        yemb_kernel<<<251, 512>>>(emb, out, t);
    }
}

// round 8
// speedup vs baseline: 1.4372x; 1.4372x over previous
#include <cuda_runtime.h>
#include <math.h>

#define BB   4
#define SS   64
#define DDIM 512
#define HH   8
#define DH   64
#define DFF  2048
#define LLAY 2
#define VV   32128
#define TT   16
#define NEGV (-1e9f)

#define GF_RES  1
#define GF_RELU 2

#define NB 148
#define NT 512

// ---------------- scratch (device globals; no allocations) ----------------
__device__ float g_x  [BB*SS*DDIM];
__device__ float g_h  [BB*SS*DDIM];
__device__ float g_q  [BB*SS*DDIM];
__device__ float g_k  [BB*SS*DDIM];
__device__ float g_v  [BB*SS*DDIM];
__device__ float g_at [BB*SS*DDIM];
__device__ float g_ff [BB*SS*DFF];
__device__ float g_hs [BB*SS*DDIM];
__device__ float g_ckc[LLAY*BB*SS*DDIM];
__device__ float g_cvc[LLAY*BB*SS*DDIM];
__device__ float g_skc[LLAY*BB*TT*DDIM];
__device__ float g_svc[LLAY*BB*TT*DDIM];
__device__ float g_xd [BB*DDIM];
__device__ float g_qd [BB*DDIM];
__device__ float g_ad [BB*DDIM];
__device__ float g_fd [BB*DFF];
__device__ float g_logits[BB*VV];

__device__ unsigned g_barcnt = 0;
__device__ unsigned g_bargen = 0;

// ======================= encoder kernels (unchanged, known-good) =======================
__global__ void embed_kernel(const int* __restrict__ ids, const float* __restrict__ emb) {
    int row = blockIdx.x;
    int id  = ids[row];
    for (int d = threadIdx.x; d < DDIM; d += 256)
        g_x[row*DDIM + d] = emb[(size_t)id*DDIM + d];
}

__global__ void rmsnorm_kernel(const float* __restrict__ x, const float* __restrict__ w,
                               float* __restrict__ o) {
    int r = blockIdx.x, tid = threadIdx.x;
    __shared__ float red[256];
    float a = x[r*DDIM + tid];
    float b = x[r*DDIM + 256 + tid];
    red[tid] = a*a + b*b;
    __syncthreads();
    for (int s = 128; s > 0; s >>= 1) { if (tid < s) red[tid] += red[tid+s]; __syncthreads(); }
    float inv = rsqrtf(red[0] / (float)DDIM + 1e-6f);
    o[r*DDIM + tid]       = a * inv * w[tid];
    o[r*DDIM + 256 + tid] = b * inv * w[256 + tid];
}

__global__ void gemm_tiled(const float* __restrict__ A, const float* __restrict__ W,
                           const float* __restrict__ res, float* __restrict__ C,
                           int M, int N, int K, int flags) {
    __shared__ float As[16][64];
    __shared__ float Bs[16][64];
    int row0 = blockIdx.y * 64, col0 = blockIdx.x * 64;
    int tid = threadIdx.x;
    int ty = tid / 16, tx = tid % 16;
    float acc[4][4];
    #pragma unroll
    for (int i = 0; i < 4; i++)
        #pragma unroll
        for (int j = 0; j < 4; j++) acc[i][j] = 0.f;

    for (int k0 = 0; k0 < K; k0 += 16) {
        #pragma unroll
        for (int p = 0; p < 4; p++) {
            int i = tid + p*256;
            int r = i >> 4, c = i & 15;
            As[c][r] = A[(row0 + r)*K + k0 + c];
        }
        #pragma unroll
        for (int p = 0; p < 4; p++) {
            int i = tid + p*256;
            int r = i >> 6, c = i & 63;
            Bs[r][c] = W[(size_t)(k0 + r)*N + col0 + c];
        }
        __syncthreads();
        #pragma unroll
        for (int k = 0; k < 16; k++) {
            float a[4], b[4];
            #pragma unroll
            for (int i = 0; i < 4; i++) a[i] = As[k][ty*4 + i];
            #pragma unroll
            for (int j = 0; j < 4; j++) b[j] = Bs[k][tx*4 + j];
            #pragma unroll
            for (int i = 0; i < 4; i++)
                #pragma unroll
                for (int j = 0; j < 4; j++) acc[i][j] += a[i]*b[j];
        }
        __syncthreads();
    }
    #pragma unroll
    for (int i = 0; i < 4; i++) {
        int r = row0 + ty*4 + i;
        #pragma unroll
        for (int j = 0; j < 4; j++) {
            int c = col0 + tx*4 + j;
            float v = acc[i][j];
            if (flags & GF_RES)  v += res[(size_t)r*N + c];
            if (flags & GF_RELU) v = fmaxf(v, 0.f);
            C[(size_t)r*N + c] = v;
        }
    }
}

__global__ void enc_attn(const float* __restrict__ Q, const float* __restrict__ K,
                         const float* __restrict__ V, const float* __restrict__ mask,
                         float* __restrict__ O) {
    int bh = blockIdx.x; int b = bh >> 3, h = bh & 7;
    int tid = threadIdx.x;
    __shared__ float Ks[64*65], Vs[64*65], sc[64], se[64];
    for (int i = tid; i < 4096; i += 64) {
        int r = i >> 6, c = i & 63;
        Ks[r*65 + c] = K[(size_t)(b*SS + r)*DDIM + h*DH + c];
        Vs[r*65 + c] = V[(size_t)(b*SS + r)*DDIM + h*DH + c];
    }
    __syncthreads();
    float bias = (1.f - mask[b*SS + tid]) * NEGV;
    for (int q = 0; q < SS; q++) {
        const float* qr = &Q[(size_t)(b*SS + q)*DDIM + h*DH];
        float s = 0.f;
        #pragma unroll 8
        for (int d = 0; d < DH; d++) s += qr[d]*Ks[tid*65 + d];
        sc[tid] = s * 0.125f + bias;
        __syncthreads();
        float mx = -1e30f;
        for (int j = 0; j < 64; j++) mx = fmaxf(mx, sc[j]);
        se[tid] = expf(sc[tid] - mx);
        __syncthreads();
        float den = 0.f;
        for (int j = 0; j < 64; j++) den += se[j];
        float o = 0.f;
        #pragma unroll 8
        for (int j = 0; j < 64; j++) o += se[j]*Vs[j*65 + tid];
        O[(size_t)(b*SS + q)*DDIM + h*DH + tid] = o / den;
        __syncthreads();
    }
}

// ======================= decode megakernel =======================
__shared__ float s_xs[4*DFF];      // 32KB
__shared__ float s_red[2048];      // 8KB
__shared__ float s_ssq[4];
__shared__ float s_sinv[4];
__shared__ float s_sc[64];
__shared__ float s_se[64];

__device__ __forceinline__ void gridbar() {
    __syncthreads();
    if (threadIdx.x == 0) {
        __threadfence();
        unsigned my = *(volatile unsigned*)&g_bargen;
        unsigned a = atomicAdd(&g_barcnt, 1u);
        if (a == gridDim.x - 1) {
            atomicExch(&g_barcnt, 0u);
            __threadfence();
            *(volatile unsigned*)&g_bargen = my + 1u;
        } else {
            while (*(volatile unsigned*)&g_bargen == my) __nanosleep(32);
            __threadfence();
        }
    }
    __syncthreads();
}

// prepare xs[4,K] in shared. mode: 0 plain, 1 ln(+sinv), 2 relu
__device__ __forceinline__ void prep_xs(const float* __restrict__ x,
                                        const float* __restrict__ ln,
                                        int kshift, int mode) {
    int K = 1 << kshift;
    if (threadIdx.x < 4) s_ssq[threadIdx.x] = 0.f;
    __syncthreads();
    float ls0=0.f, ls1=0.f, ls2=0.f, ls3=0.f;
    for (int i = threadIdx.x; i < 4*K; i += NT) {
        int m = i >> kshift, k = i & (K-1);
        float v = x[i];
        if (mode == 1) {
            float vv = v*v;
            if (m==0) ls0+=vv; else if (m==1) ls1+=vv; else if (m==2) ls2+=vv; else ls3+=vv;
            s_xs[i] = v * ln[k];
        } else if (mode == 2) {
            s_xs[i] = fmaxf(v, 0.f);
        } else {
            s_xs[i] = v;
        }
    }
    if (mode == 1) {
        atomicAdd(&s_ssq[0], ls0); atomicAdd(&s_ssq[1], ls1);
        atomicAdd(&s_ssq[2], ls2); atomicAdd(&s_ssq[3], ls3);
    }
    __syncthreads();
    if (threadIdx.x < 4)
        s_sinv[threadIdx.x] = (mode == 1) ? rsqrtf(s_ssq[threadIdx.x]/(float)(1<<kshift) + 1e-6f) : 1.f;
    __syncthreads();
}

// one 16-col tile of out[4,N] = (xs @ W[K,N]) * sinv? + res?
__device__ __forceinline__ void gemv_tile(const float* __restrict__ W, int K, int N, int tile,
                                          float* __restrict__ dst, int mstride,
                                          const float* __restrict__ res, int rstride,
                                          bool use_sinv) {
    int col = threadIdx.x & 15;
    int ks  = threadIdx.x >> 4;     // 0..31
    int kc  = K >> 5;
    int c = tile*16 + col;
    float a0=0.f, a1=0.f, a2=0.f, a3=0.f;
    const float* xp = s_xs + ks*kc;
    const float* wp = W + (size_t)(ks*kc)*N + c;
    #pragma unroll 4
    for (int k = 0; k < kc; k++) {
        float w = wp[(size_t)k*N];
        a0 += xp[k]*w; a1 += xp[K+k]*w; a2 += xp[2*K+k]*w; a3 += xp[3*K+k]*w;
    }
    int base = ks*64 + col*4;
    s_red[base+0]=a0; s_red[base+1]=a1; s_red[base+2]=a2; s_red[base+3]=a3;
    __syncthreads();
    #pragma unroll
    for (int s = 16; s > 0; s >>= 1) {
        if (ks < s) {
            int b2 = (ks+s)*64 + col*4;
            s_red[base+0] += s_red[b2+0]; s_red[base+1] += s_red[b2+1];
            s_red[base+2] += s_red[b2+2]; s_red[base+3] += s_red[b2+3];
        }
        __syncthreads();
    }
    if (ks == 0) {
        #pragma unroll
        for (int m = 0; m < 4; m++) {
            float v = s_red[col*4 + m];
            if (use_sinv) v *= s_sinv[m];
            if (res) v += res[(size_t)m*rstride + c];
            dst[(size_t)m*mstride + c] = v;
        }
    }
    __syncthreads();
}

__device__ __forceinline__ void gemv_all(const float* __restrict__ W, int K, int N,
                                         float* __restrict__ dst, int mstride,
                                         const float* __restrict__ res, int rstride,
                                         bool use_sinv) {
    int nt = N >> 4;
    for (int t0 = blockIdx.x; t0 < nt; t0 += gridDim.x)
        gemv_tile(W, K, N, t0, dst, mstride, res, rstride, use_sinv);
}

__global__ void __launch_bounds__(NT, 1)
decode_megakernel(const float* __restrict__ mask, const float* __restrict__ emb,
                  const float* __restrict__ sq, const float* __restrict__ sk,
                  const float* __restrict__ sv, const float* __restrict__ so,
                  const float* __restrict__ ln1, const float* __restrict__ cq,
                  const float* __restrict__ co, const float* __restrict__ ln2,
                  const float* __restrict__ w1, const float* __restrict__ w2,
                  const float* __restrict__ ln3, const float* __restrict__ lnf,
                  const float* __restrict__ lm, float* __restrict__ out) {
    const size_t DD2 = (size_t)DDIM*DDIM;
    const size_t DF  = (size_t)DDIM*DFF;
    int tid = threadIdx.x;

    // init: y0 = emb[PAD_ID=0]
    if (blockIdx.x < 4)
        g_xd[blockIdx.x*DDIM + tid] = emb[tid];
    gridbar();

    for (int t = 0; t < TT; t++) {
        for (int l = 0; l < LLAY; l++) {
            // ---- stage 1: rms(ln1) + QKV (96 tiles) ----
            prep_xs(g_xd, ln1 + l*DDIM, 9, 1);
            for (int tt = blockIdx.x; tt < 96; tt += gridDim.x) {
                int seg = tt >> 5, ti = tt & 31;
                if (seg == 0) {
                    gemv_tile(sq + l*DD2, DDIM, DDIM, ti, g_qd, DDIM, nullptr, 0, true);
                } else if (seg == 1) {
                    gemv_tile(sk + l*DD2, DDIM, DDIM, ti,
                              g_skc + (size_t)(l*BB*TT + t)*DDIM, TT*DDIM, nullptr, 0, true);
                } else {
                    gemv_tile(sv + l*DD2, DDIM, DDIM, ti,
                              g_svc + (size_t)(l*BB*TT + t)*DDIM, TT*DDIM, nullptr, 0, true);
                }
            }
            gridbar();

            // ---- stage 2: self-attention (t+1 keys) ----
            if (blockIdx.x < 32) {
                int b = blockIdx.x >> 3, h = blockIdx.x & 7;
                int nk = t + 1;
                const float* q = g_qd + b*DDIM + h*DH;
                if (tid < nk) {
                    const float* kr = g_skc + (size_t)((l*BB + b)*TT + tid)*DDIM + h*DH;
                    float s = 0.f;
                    #pragma unroll 8
                    for (int d = 0; d < DH; d++) s += q[d]*kr[d];
                    s_sc[tid] = s * 0.125f;
                }
                __syncthreads();
                if (tid < nk) {
                    float mx = -1e30f;
                    for (int j = 0; j < nk; j++) mx = fmaxf(mx, s_sc[j]);
                    s_se[tid] = expf(s_sc[tid] - mx);
                }
                __syncthreads();
                if (tid < 64) {
                    float den = 0.f, o = 0.f;
                    for (int j = 0; j < nk; j++) {
                        den += s_se[j];
                        o += s_se[j]*g_svc[(size_t)((l*BB + b)*TT + j)*DDIM + h*DH + tid];
                    }
                    g_ad[b*DDIM + h*DH + tid] = o / den;
                }
            }
            gridbar();

            // ---- stage 3: O-proj + residual into g_xd ----
            prep_xs(g_ad, nullptr, 9, 0);
            gemv_all(so + l*DD2, DDIM, DDIM, g_xd, DDIM, g_xd, DDIM, false);
            gridbar();

            // ---- stage 4: rms(ln2) + cross-Q ----
            prep_xs(g_xd, ln2 + l*DDIM, 9, 1);
            gemv_all(cq + l*DD2, DDIM, DDIM, g_qd, DDIM, nullptr, 0, true);
            gridbar();

            // ---- stage 5: cross-attention (64 enc keys) ----
            if (blockIdx.x < 32) {
                int b = blockIdx.x >> 3, h = blockIdx.x & 7;
                const float* q = g_qd + b*DDIM + h*DH;
                if (tid < 64) {
                    const float* kr = g_ckc + (size_t)((l*BB + b)*SS + tid)*DDIM + h*DH;
                    float s = 0.f;
                    #pragma unroll 8
                    for (int d = 0; d < DH; d++) s += q[d]*kr[d];
                    s_sc[tid] = s * 0.125f + (1.f - mask[b*SS + tid]) * NEGV;
                }
                __syncthreads();
                if (tid < 64) {
                    float mx = -1e30f;
                    for (int j = 0; j < 64; j++) mx = fmaxf(mx, s_sc[j]);
                    s_se[tid] = expf(s_sc[tid] - mx);
                }
                __syncthreads();
                if (tid < 64) {
                    float den = 0.f, o = 0.f;
                    #pragma unroll 8
                    for (int j = 0; j < 64; j++) {
                        den += s_se[j];
                        o += s_se[j]*g_cvc[(size_t)((l*BB + b)*SS + j)*DDIM + h*DH + tid];
                    }
                    g_ad[b*DDIM + h*DH + tid] = o / den;
                }
            }
            gridbar();

            // ---- stage 6: cross O-proj + residual ----
            prep_xs(g_ad, nullptr, 9, 0);
            gemv_all(co + l*DD2, DDIM, DDIM, g_xd, DDIM, g_xd, DDIM, false);
            gridbar();

            // ---- stage 7: rms(ln3) + W1 (pre-activation; relu applied on read) ----
            prep_xs(g_xd, ln3 + l*DDIM, 9, 1);
            gemv_all(w1 + l*DF, DDIM, DFF, g_fd, DFF, nullptr, 0, true);
            gridbar();

            // ---- stage 8: relu + W2 + residual ----
            prep_xs(g_fd, nullptr, 11, 2);
            gemv_all(w2 + l*DF, DFF, DDIM, g_xd, DDIM, g_xd, DDIM, false);
            gridbar();
        }

        // ---- logits: rms(lnf) @ lm_head ----
        prep_xs(g_xd, lnf, 9, 1);
        gemv_all(lm, DDIM, VV, g_logits, VV, nullptr, 0, true);
        gridbar();

        // ---- softmax + argmax + write probs/pred + zero g_xd ----
        if (blockIdx.x < 4) {
            int b = blockIdx.x;
            const float* lg = g_logits + (size_t)b*VV;
            int* sidx = (int*)s_xs;
            float mx = -1e30f; int mi = 0;
            for (int v = tid; v < VV; v += NT) {
                float f = lg[v];
                if (f > mx) { mx = f; mi = v; }
            }
            s_red[tid] = mx; sidx[tid] = mi;
            __syncthreads();
            for (int s = 256; s > 0; s >>= 1) {
                if (tid < s) {
                    float o = s_red[tid + s]; int oi = sidx[tid + s];
                    if (o > s_red[tid] || (o == s_red[tid] && oi < sidx[tid])) {
                        s_red[tid] = o; sidx[tid] = oi;
                    }
                }
                __syncthreads();
            }
            float M = s_red[0]; int am = sidx[0];
            __syncthreads();
            float sum = 0.f;
            for (int v = tid; v < VV; v += NT) sum += expf(lg[v] - M);
            s_red[tid] = sum;
            __syncthreads();
            for (int s = 256; s > 0; s >>= 1) { if (tid < s) s_red[tid] += s_red[tid + s]; __syncthreads(); }
            float inv = 1.f / s_red[0];
            float* pr = out + (size_t)(b*TT + t)*VV;
            for (int v = tid; v < VV; v += NT) pr[v] = expf(lg[v] - M) * inv;
            if (tid == 0)
                out[(size_t)BB*TT*VV + b*TT + t] = (am == 0) ? 1.0f : 0.0f;
            g_xd[b*DDIM + tid] = 0.f;
        }
        gridbar();

        // ---- soft embedding: g_xd += probs @ emb (skip on last iter) ----
        if (t + 1 < TT) {
            float a0=0.f, a1=0.f, a2=0.f, a3=0.f;
            int d = tid;
            for (int t0 = blockIdx.x; t0 < VV/128; t0 += gridDim.x) {
                int v0 = t0*128;
                __syncthreads();
                {
                    int m = tid >> 7, j = tid & 127;
                    s_red[tid] = out[(size_t)(m*TT + t)*VV + v0 + j];
                }
                __syncthreads();
                #pragma unroll 4
                for (int j = 0; j < 128; j++) {
                    float e = emb[(size_t)(v0 + j)*DDIM + d];
                    a0 += s_red[j]*e; a1 += s_red[128+j]*e;
                    a2 += s_red[256+j]*e; a3 += s_red[384+j]*e;
                }
            }
            atomicAdd(&g_xd[0*DDIM + d], a0);
            atomicAdd(&g_xd[1*DDIM + d], a1);
            atomicAdd(&g_xd[2*DDIM + d], a2);
            atomicAdd(&g_xd[3*DDIM + d], a3);
            gridbar();
        }
    }
}

// ---------------- launcher ----------------
extern "C" void kernel_launch(void* const* d_in, const int* in_sizes, int n_in,
                              void* d_out, int out_size) {
    const int*   ids     = (const int*)  d_in[0];
    const float* mask    = (const float*)d_in[1];
    const float* emb     = (const float*)d_in[2];
    const float* enc_wq  = (const float*)d_in[3];
    const float* enc_wk  = (const float*)d_in[4];
    const float* enc_wv  = (const float*)d_in[5];
    const float* enc_wo  = (const float*)d_in[6];
    const float* enc_ln1 = (const float*)d_in[7];
    const float* enc_w1  = (const float*)d_in[8];
    const float* enc_w2  = (const float*)d_in[9];
    const float* enc_ln2 = (const float*)d_in[10];
    const float* enc_lnf = (const float*)d_in[11];
    const float* dec_sq  = (const float*)d_in[12];
    const float* dec_sk  = (const float*)d_in[13];
    const float* dec_sv  = (const float*)d_in[14];
    const float* dec_so  = (const float*)d_in[15];
    const float* dec_ln1 = (const float*)d_in[16];
    const float* dec_cq  = (const float*)d_in[17];
    const float* dec_ck  = (const float*)d_in[18];
    const float* dec_cv  = (const float*)d_in[19];
    const float* dec_co  = (const float*)d_in[20];
    const float* dec_ln2 = (const float*)d_in[21];
    const float* dec_w1  = (const float*)d_in[22];
    const float* dec_w2  = (const float*)d_in[23];
    const float* dec_ln3 = (const float*)d_in[24];
    const float* dec_lnf = (const float*)d_in[25];
    const float* lm      = (const float*)d_in[26];
    float* out = (float*)d_out;

    float *gx, *gh, *gq, *gk, *gv, *gat, *gff, *ghs, *gckc, *gcvc;
    cudaGetSymbolAddress((void**)&gx,   g_x);
    cudaGetSymbolAddress((void**)&gh,   g_h);
    cudaGetSymbolAddress((void**)&gq,   g_q);
    cudaGetSymbolAddress((void**)&gk,   g_k);
    cudaGetSymbolAddress((void**)&gv,   g_v);
    cudaGetSymbolAddress((void**)&gat,  g_at);
    cudaGetSymbolAddress((void**)&gff,  g_ff);
    cudaGetSymbolAddress((void**)&ghs,  g_hs);
    cudaGetSymbolAddress((void**)&gckc, g_ckc);
    cudaGetSymbolAddress((void**)&gcvc, g_cvc);

    const int MROWS = BB*SS;
    const size_t DD2 = (size_t)DDIM*DDIM;
    const size_t DF  = (size_t)DDIM*DFF;

    // ===== encoder =====
    embed_kernel<<<MROWS, 256>>>(ids, emb);
    for (int l = 0; l < LLAY; l++) {
        rmsnorm_kernel<<<MROWS, 256>>>(gx, enc_ln1 + l*DDIM, gh);
        dim3 g8(8, 4), g32(32, 4);
        gemm_tiled<<<g8, 256>>>(gh, enc_wq + l*DD2, nullptr, gq, MROWS, DDIM, DDIM, 0);
        gemm_tiled<<<g8, 256>>>(gh, enc_wk + l*DD2, nullptr, gk, MROWS, DDIM, DDIM, 0);
        gemm_tiled<<<g8, 256>>>(gh, enc_wv + l*DD2, nullptr, gv, MROWS, DDIM, DDIM, 0);
        enc_attn<<<BB*HH, 64>>>(gq, gk, gv, mask, gat);
        gemm_tiled<<<g8, 256>>>(gat, enc_wo + l*DD2, gx, gx, MROWS, DDIM, DDIM, GF_RES);
        rmsnorm_kernel<<<MROWS, 256>>>(gx, enc_ln2 + l*DDIM, gh);
        gemm_tiled<<<g32, 256>>>(gh, enc_w1 + l*DF, nullptr, gff, MROWS, DFF, DDIM, GF_RELU);
        gemm_tiled<<<g8, 256>>>(gff, enc_w2 + l*DF, gx, gx, MROWS, DDIM, DFF, GF_RES);
    }
    rmsnorm_kernel<<<MROWS, 256>>>(gx, enc_lnf, ghs);

    // cross K/V precompute
    for (int l = 0; l < LLAY; l++) {
        dim3 g8(8, 4);
        gemm_tiled<<<g8, 256>>>(ghs, dec_ck + l*DD2, nullptr, gckc + (size_t)l*MROWS*DDIM,
                                MROWS, DDIM, DDIM, 0);
        gemm_tiled<<<g8, 256>>>(ghs, dec_cv + l*DD2, nullptr, gcvc + (size_t)l*MROWS*DDIM,
                                MROWS, DDIM, DDIM, 0);
    }

    // ===== full 16-iteration decode in ONE persistent kernel =====
    decode_megakernel<<<NB, NT>>>(mask, emb,
                                  dec_sq, dec_sk, dec_sv, dec_so, dec_ln1,
                                  dec_cq, dec_co, dec_ln2,
                                  dec_w1, dec_w2, dec_ln3, dec_lnf,
                                  lm, out);
}

// round 9
// speedup vs baseline: 1.7698x; 1.2314x over previous
#include <cuda_runtime.h>
#include <math.h>

#define BB   4
#define SS   64
#define DDIM 512
#define HH   8
#define DH   64
#define DFF  2048
#define LLAY 2
#define VV   32128
#define TT   16
#define NEGV (-1e9f)

#define GF_RES  1
#define GF_RELU 2

#define NB 148
#define NT 512

// ---------------- scratch (device globals; no allocations) ----------------
__device__ float g_x  [BB*SS*DDIM];
__device__ float g_h  [BB*SS*DDIM];
__device__ float g_q  [BB*SS*DDIM];
__device__ float g_k  [BB*SS*DDIM];
__device__ float g_v  [BB*SS*DDIM];
__device__ float g_at [BB*SS*DDIM];
__device__ float g_ff [BB*SS*DFF];
__device__ float g_hs [BB*SS*DDIM];
__device__ float g_ckc[LLAY*BB*SS*DDIM];
__device__ float g_cvc[LLAY*BB*SS*DDIM];
__device__ float g_skc[LLAY*BB*TT*DDIM];
__device__ float g_svc[LLAY*BB*TT*DDIM];
__device__ float g_xd [BB*DDIM];
__device__ float g_qd [BB*DDIM];
__device__ float g_ad [BB*DDIM];
__device__ float g_fd [BB*DFF];
__device__ float g_logits[BB*VV];
__device__ float g_part[1048576];   // k-split partials (max 8 * 256*512 or 2 * 256*2048)

__device__ unsigned g_barcnt = 0;
__device__ unsigned g_bargen = 0;

// ======================= encoder kernels =======================
__global__ void embed_kernel(const int* __restrict__ ids, const float* __restrict__ emb) {
    int row = blockIdx.x;
    int id  = ids[row];
    for (int d = threadIdx.x; d < DDIM; d += 256)
        g_x[row*DDIM + d] = emb[(size_t)id*DDIM + d];
}

__global__ void rmsnorm_kernel(const float* __restrict__ x, const float* __restrict__ w,
                               float* __restrict__ o) {
    int r = blockIdx.x, tid = threadIdx.x;
    __shared__ float red[256];
    float a = x[r*DDIM + tid];
    float b = x[r*DDIM + 256 + tid];
    red[tid] = a*a + b*b;
    __syncthreads();
    for (int s = 128; s > 0; s >>= 1) { if (tid < s) red[tid] += red[tid+s]; __syncthreads(); }
    float inv = rsqrtf(red[0] / (float)DDIM + 1e-6f);
    o[r*DDIM + tid]       = a * inv * w[tid];
    o[r*DDIM + 256 + tid] = b * inv * w[256 + tid];
}

// k-split GEMM: part[ks] += A[M,K(ks-slice)] @ W[K,N]; no epilogue
__global__ void gemm_split(const float* __restrict__ A, const float* __restrict__ W,
                           float* __restrict__ part, int M, int N, int K, int KS) {
    __shared__ float As[16][64];
    __shared__ float Bs[16][64];
    int row0 = blockIdx.y * 64, col0 = blockIdx.x * 64;
    int ksid = blockIdx.z;
    int kc = K / KS;
    int kbeg = ksid * kc, kend = kbeg + kc;
    int tid = threadIdx.x;
    int ty = tid / 16, tx = tid % 16;
    float acc[4][4];
    #pragma unroll
    for (int i = 0; i < 4; i++)
        #pragma unroll
        for (int j = 0; j < 4; j++) acc[i][j] = 0.f;

    for (int k0 = kbeg; k0 < kend; k0 += 16) {
        #pragma unroll
        for (int p = 0; p < 4; p++) {
            int i = tid + p*256;
            int r = i >> 4, c = i & 15;
            As[c][r] = A[(row0 + r)*K + k0 + c];
        }
        #pragma unroll
        for (int p = 0; p < 4; p++) {
            int i = tid + p*256;
            int r = i >> 6, c = i & 63;
            Bs[r][c] = W[(size_t)(k0 + r)*N + col0 + c];
        }
        __syncthreads();
        #pragma unroll
        for (int k = 0; k < 16; k++) {
            float a[4], b[4];
            #pragma unroll
            for (int i = 0; i < 4; i++) a[i] = As[k][ty*4 + i];
            #pragma unroll
            for (int j = 0; j < 4; j++) b[j] = Bs[k][tx*4 + j];
            #pragma unroll
            for (int i = 0; i < 4; i++)
                #pragma unroll
                for (int j = 0; j < 4; j++) acc[i][j] += a[i]*b[j];
        }
        __syncthreads();
    }
    float* pc = part + (size_t)ksid * M * N;
    #pragma unroll
    for (int i = 0; i < 4; i++) {
        int r = row0 + ty*4 + i;
        #pragma unroll
        for (int j = 0; j < 4; j++)
            pc[(size_t)r*N + col0 + tx*4 + j] = acc[i][j];
    }
}

// reduce KS partials + epilogue
__global__ void gemm_reduce(const float* __restrict__ part, const float* __restrict__ res,
                            float* __restrict__ C, int MN, int KS, int flags) {
    int i = (blockIdx.x*256 + threadIdx.x) * 4;
    if (i >= MN) return;
    float4 s = *(const float4*)(part + i);
    for (int k = 1; k < KS; k++) {
        float4 p = *(const float4*)(part + (size_t)k*MN + i);
        s.x += p.x; s.y += p.y; s.z += p.z; s.w += p.w;
    }
    if (flags & GF_RES) {
        float4 r = *(const float4*)(res + i);
        s.x += r.x; s.y += r.y; s.z += r.z; s.w += r.w;
    }
    if (flags & GF_RELU) {
        s.x = fmaxf(s.x, 0.f); s.y = fmaxf(s.y, 0.f);
        s.z = fmaxf(s.z, 0.f); s.w = fmaxf(s.w, 0.f);
    }
    *(float4*)(C + i) = s;
}

__global__ void enc_attn(const float* __restrict__ Q, const float* __restrict__ K,
                         const float* __restrict__ V, const float* __restrict__ mask,
                         float* __restrict__ O) {
    int bh = blockIdx.x; int b = bh >> 3, h = bh & 7;
    int tid = threadIdx.x;
    __shared__ float Ks[64*65], Vs[64*65], sc[64], se[64];
    for (int i = tid; i < 4096; i += 64) {
        int r = i >> 6, c = i & 63;
        Ks[r*65 + c] = K[(size_t)(b*SS + r)*DDIM + h*DH + c];
        Vs[r*65 + c] = V[(size_t)(b*SS + r)*DDIM + h*DH + c];
    }
    __syncthreads();
    float bias = (1.f - mask[b*SS + tid]) * NEGV;
    for (int q = 0; q < SS; q++) {
        const float* qr = &Q[(size_t)(b*SS + q)*DDIM + h*DH];
        float s = 0.f;
        #pragma unroll 8
        for (int d = 0; d < DH; d++) s += qr[d]*Ks[tid*65 + d];
        sc[tid] = s * 0.125f + bias;
        __syncthreads();
        float mx = -1e30f;
        for (int j = 0; j < 64; j++) mx = fmaxf(mx, sc[j]);
        se[tid] = expf(sc[tid] - mx);
        __syncthreads();
        float den = 0.f;
        for (int j = 0; j < 64; j++) den += se[j];
        float o = 0.f;
        #pragma unroll 8
        for (int j = 0; j < 64; j++) o += se[j]*Vs[j*65 + tid];
        O[(size_t)(b*SS + q)*DDIM + h*DH + tid] = o / den;
        __syncthreads();
    }
}

// ======================= decode megakernel =======================
__shared__ float s_xs[4*DFF];      // 32KB
__shared__ float s_red[2048];      // 8KB
__shared__ float s_ssq[4];
__shared__ float s_sinv[4];
__shared__ float s_sc[64];
__shared__ float s_se[64];

__device__ __forceinline__ void gridbar() {
    __syncthreads();
    if (threadIdx.x == 0) {
        __threadfence();
        unsigned my = *(volatile unsigned*)&g_bargen;
        unsigned a = atomicAdd(&g_barcnt, 1u);
        if (a == gridDim.x - 1) {
            atomicExch(&g_barcnt, 0u);
            __threadfence();
            *(volatile unsigned*)&g_bargen = my + 1u;
        } else {
            while (*(volatile unsigned*)&g_bargen == my) __nanosleep(32);
            __threadfence();   // CCTL.IVALL: invalidate this SM's L1 before reading peer writes
        }
    }
    __syncthreads();
}

// prepare xs[4,K] in shared. mode: 0 plain, 1 ln(+sinv), 2 relu
__device__ __forceinline__ void prep_xs(const float* __restrict__ x,
                                        const float* __restrict__ ln,
                                        int kshift, int mode) {
    int K = 1 << kshift;
    if (threadIdx.x < 4) s_ssq[threadIdx.x] = 0.f;
    __syncthreads();
    float ls0=0.f, ls1=0.f, ls2=0.f, ls3=0.f;
    for (int i = threadIdx.x; i < 4*K; i += NT) {
        int m = i >> kshift, k = i & (K-1);
        float v = x[i];
        if (mode == 1) {
            float vv = v*v;
            if (m==0) ls0+=vv; else if (m==1) ls1+=vv; else if (m==2) ls2+=vv; else ls3+=vv;
            s_xs[i] = v * ln[k];
        } else if (mode == 2) {
            s_xs[i] = fmaxf(v, 0.f);
        } else {
            s_xs[i] = v;
        }
    }
    if (mode == 1) {
        atomicAdd(&s_ssq[0], ls0); atomicAdd(&s_ssq[1], ls1);
        atomicAdd(&s_ssq[2], ls2); atomicAdd(&s_ssq[3], ls3);
    }
    __syncthreads();
    if (threadIdx.x < 4)
        s_sinv[threadIdx.x] = (mode == 1) ? rsqrtf(s_ssq[threadIdx.x]/(float)(1<<kshift) + 1e-6f) : 1.f;
    __syncthreads();
}

// one 16-col tile of out[4,N] = (xs @ W[K,N]) * sinv? + res?
// Fully unrolled loads (MLP=KC), shuffle reduction, only 2 block syncs.
template<int K>
__device__ __forceinline__ void gemv_tile(const float* __restrict__ W, int N, int tile,
                                          float* __restrict__ dst, int mstride,
                                          const float* __restrict__ res, int rstride,
                                          bool use_sinv) {
    constexpr int KC = K / 32;
    int tid = threadIdx.x;
    int w = tid >> 5, lane = tid & 31;
    int sub = lane >> 4, c = lane & 15;
    int ks = w*2 + sub;                 // 0..31
    int col = tile*16 + c;
    const float* xp = s_xs + ks*KC;
    const float* wp = W + (size_t)(ks*KC)*N + col;
    float a0=0.f, a1=0.f, a2=0.f, a3=0.f;
    #pragma unroll
    for (int k = 0; k < KC; k++) {
        float wv = wp[(size_t)k*N];
        a0 += xp[k]*wv; a1 += xp[K+k]*wv; a2 += xp[2*K+k]*wv; a3 += xp[3*K+k]*wv;
    }
    a0 += __shfl_xor_sync(0xffffffffu, a0, 16);
    a1 += __shfl_xor_sync(0xffffffffu, a1, 16);
    a2 += __shfl_xor_sync(0xffffffffu, a2, 16);
    a3 += __shfl_xor_sync(0xffffffffu, a3, 16);
    if (sub == 0) {
        s_red[(c*4+0)*17 + w] = a0;
        s_red[(c*4+1)*17 + w] = a1;
        s_red[(c*4+2)*17 + w] = a2;
        s_red[(c*4+3)*17 + w] = a3;
    }
    __syncthreads();
    if (tid < 64) {
        float s = 0.f;
        #pragma unroll
        for (int w2 = 0; w2 < 16; w2++) s += s_red[tid*17 + w2];
        int cc = tid >> 2, m = tid & 3;
        int oc = tile*16 + cc;
        if (use_sinv) s *= s_sinv[m];
        if (res) s += res[(size_t)m*rstride + oc];
        dst[(size_t)m*mstride + oc] = s;
    }
    __syncthreads();
}

template<int K>
__device__ __forceinline__ void gemv_all(const float* __restrict__ W, int N,
                                         float* __restrict__ dst, int mstride,
                                         const float* __restrict__ res, int rstride,
                                         bool use_sinv) {
    int nt = N >> 4;
    for (int t0 = blockIdx.x; t0 < nt; t0 += gridDim.x)
        gemv_tile<K>(W, N, t0, dst, mstride, res, rstride, use_sinv);
}

__global__ void __launch_bounds__(NT, 1)
decode_megakernel(const float* __restrict__ mask, const float* __restrict__ emb,
                  const float* __restrict__ sq, const float* __restrict__ sk,
                  const float* __restrict__ sv, const float* __restrict__ so,
                  const float* __restrict__ ln1, const float* __restrict__ cq,
                  const float* __restrict__ co, const float* __restrict__ ln2,
                  const float* __restrict__ w1, const float* __restrict__ w2,
                  const float* __restrict__ ln3, const float* __restrict__ lnf,
                  const float* __restrict__ lm, float* __restrict__ out) {
    const size_t DD2 = (size_t)DDIM*DDIM;
    const size_t DF  = (size_t)DDIM*DFF;
    int tid = threadIdx.x;

    if (blockIdx.x < 4)
        g_xd[blockIdx.x*DDIM + tid] = emb[tid];
    gridbar();

    for (int t = 0; t < TT; t++) {
        for (int l = 0; l < LLAY; l++) {
            // ---- stage 1: rms(ln1) + QKV (96 tiles) ----
            prep_xs(g_xd, ln1 + l*DDIM, 9, 1);
            for (int tt = blockIdx.x; tt < 96; tt += gridDim.x) {
                int seg = tt >> 5, ti = tt & 31;
                if (seg == 0) {
                    gemv_tile<DDIM>(sq + l*DD2, DDIM, ti, g_qd, DDIM, nullptr, 0, true);
                } else if (seg == 1) {
                    gemv_tile<DDIM>(sk + l*DD2, DDIM, ti,
                                    g_skc + (size_t)(l*BB*TT + t)*DDIM, TT*DDIM, nullptr, 0, true);
                } else {
                    gemv_tile<DDIM>(sv + l*DD2, DDIM, ti,
                                    g_svc + (size_t)(l*BB*TT + t)*DDIM, TT*DDIM, nullptr, 0, true);
                }
            }
            gridbar();

            // ---- stage 2: self-attention (t+1 keys) ----
            if (blockIdx.x < 32) {
                int b = blockIdx.x >> 3, h = blockIdx.x & 7;
                int nk = t + 1;
                const float* q = g_qd + b*DDIM + h*DH;
                if (tid < nk) {
                    const float* kr = g_skc + (size_t)((l*BB + b)*TT + tid)*DDIM + h*DH;
                    float s = 0.f;
                    #pragma unroll 16
                    for (int d = 0; d < DH; d++) s += q[d]*kr[d];
                    s_sc[tid] = s * 0.125f;
                }
                __syncthreads();
                if (tid < nk) {
                    float mx = -1e30f;
                    for (int j = 0; j < nk; j++) mx = fmaxf(mx, s_sc[j]);
                    s_se[tid] = expf(s_sc[tid] - mx);
                }
                __syncthreads();
                if (tid < 64) {
                    float den = 0.f, o = 0.f;
                    for (int j = 0; j < nk; j++) {
                        den += s_se[j];
                        o += s_se[j]*g_svc[(size_t)((l*BB + b)*TT + j)*DDIM + h*DH + tid];
                    }
                    g_ad[b*DDIM + h*DH + tid] = o / den;
                }
            }
            gridbar();

            // ---- stage 3: O-proj + residual ----
            prep_xs(g_ad, nullptr, 9, 0);
            gemv_all<DDIM>(so + l*DD2, DDIM, g_xd, DDIM, g_xd, DDIM, false);
            gridbar();

            // ---- stage 4: rms(ln2) + cross-Q ----
            prep_xs(g_xd, ln2 + l*DDIM, 9, 1);
            gemv_all<DDIM>(cq + l*DD2, DDIM, g_qd, DDIM, nullptr, 0, true);
            gridbar();

            // ---- stage 5: cross-attention ----
            if (blockIdx.x < 32) {
                int b = blockIdx.x >> 3, h = blockIdx.x & 7;
                const float* q = g_qd + b*DDIM + h*DH;
                if (tid < 64) {
                    const float* kr = g_ckc + (size_t)((l*BB + b)*SS + tid)*DDIM + h*DH;
                    float s = 0.f;
                    #pragma unroll 16
                    for (int d = 0; d < DH; d++) s += q[d]*kr[d];
                    s_sc[tid] = s * 0.125f + (1.f - mask[b*SS + tid]) * NEGV;
                }
                __syncthreads();
                if (tid < 64) {
                    float mx = -1e30f;
                    for (int j = 0; j < 64; j++) mx = fmaxf(mx, s_sc[j]);
                    s_se[tid] = expf(s_sc[tid] - mx);
                }
                __syncthreads();
                if (tid < 64) {
                    float den = 0.f, o = 0.f;
                    #pragma unroll 8
                    for (int j = 0; j < 64; j++) {
                        den += s_se[j];
                        o += s_se[j]*g_cvc[(size_t)((l*BB + b)*SS + j)*DDIM + h*DH + tid];
                    }
                    g_ad[b*DDIM + h*DH + tid] = o / den;
                }
            }
            gridbar();

            // ---- stage 6: cross O-proj + residual ----
            prep_xs(g_ad, nullptr, 9, 0);
            gemv_all<DDIM>(co + l*DD2, DDIM, g_xd, DDIM, g_xd, DDIM, false);
            gridbar();

            // ---- stage 7: rms(ln3) + W1 ----
            prep_xs(g_xd, ln3 + l*DDIM, 9, 1);
            gemv_all<DDIM>(w1 + l*DF, DFF, g_fd, DFF, nullptr, 0, true);
            gridbar();

            // ---- stage 8: relu + W2 + residual ----
            prep_xs(g_fd, nullptr, 11, 2);
            gemv_all<DFF>(w2 + l*DF, DDIM, g_xd, DDIM, g_xd, DDIM, false);
            gridbar();
        }

        // ---- logits ----
        prep_xs(g_xd, lnf, 9, 1);
        gemv_all<DDIM>(lm, VV, g_logits, VV, nullptr, 0, true);
        gridbar();

        // ---- softmax + argmax + write probs/pred + zero x_dec ----
        if (blockIdx.x < 4) {
            int b = blockIdx.x;
            const float* lg = g_logits + (size_t)b*VV;
            int* sidx = (int*)s_xs;
            float mx = -1e30f; int mi = 0;
            for (int v = tid; v < VV; v += NT) {
                float f = lg[v];
                if (f > mx) { mx = f; mi = v; }
            }
            s_red[tid] = mx; sidx[tid] = mi;
            __syncthreads();
            for (int s = 256; s > 0; s >>= 1) {
                if (tid < s) {
                    float o = s_red[tid + s]; int oi = sidx[tid + s];
                    if (o > s_red[tid] || (o == s_red[tid] && oi < sidx[tid])) {
                        s_red[tid] = o; sidx[tid] = oi;
                    }
                }
                __syncthreads();
            }
            float M = s_red[0]; int am = sidx[0];
            __syncthreads();
            float sum = 0.f;
            for (int v = tid; v < VV; v += NT) sum += expf(lg[v] - M);
            s_red[tid] = sum;
            __syncthreads();
            for (int s = 256; s > 0; s >>= 1) { if (tid < s) s_red[tid] += s_red[tid + s]; __syncthreads(); }
            float inv = 1.f / s_red[0];
            float* pr = out + (size_t)(b*TT + t)*VV;
            for (int v = tid; v < VV; v += NT) pr[v] = expf(lg[v] - M) * inv;
            if (tid == 0)
                out[(size_t)BB*TT*VV + b*TT + t] = (am == 0) ? 1.0f : 0.0f;
            g_xd[b*DDIM + tid] = 0.f;
        }
        gridbar();

        // ---- soft embedding: g_xd += probs @ emb ----
        if (t + 1 < TT) {
            float a0=0.f, a1=0.f, a2=0.f, a3=0.f;
            int d = tid;
            for (int t0 = blockIdx.x; t0 < VV/128; t0 += gridDim.x) {
                int v0 = t0*128;
                const float* p0 = out + (size_t)(0*TT + t)*VV + v0;
                const float* p1 = out + (size_t)(1*TT + t)*VV + v0;
                const float* p2 = out + (size_t)(2*TT + t)*VV + v0;
                const float* p3 = out + (size_t)(3*TT + t)*VV + v0;
                #pragma unroll 8
                for (int j = 0; j < 128; j++) {
                    float e = emb[(size_t)(v0 + j)*DDIM + d];
                    a0 += p0[j]*e; a1 += p1[j]*e; a2 += p2[j]*e; a3 += p3[j]*e;
                }
            }
            atomicAdd(&g_xd[0*DDIM + d], a0);
            atomicAdd(&g_xd[1*DDIM + d], a1);
            atomicAdd(&g_xd[2*DDIM + d], a2);
            atomicAdd(&g_xd[3*DDIM + d], a3);
            gridbar();
        }
    }
}

// ---------------- launcher ----------------
extern "C" void kernel_launch(void* const* d_in, const int* in_sizes, int n_in,
                              void* d_out, int out_size) {
    const int*   ids     = (const int*)  d_in[0];
    const float* mask    = (const float*)d_in[1];
    const float* emb     = (const float*)d_in[2];
    const float* enc_wq  = (const float*)d_in[3];
    const float* enc_wk  = (const float*)d_in[4];
    const float* enc_wv  = (const float*)d_in[5];
    const float* enc_wo  = (const float*)d_in[6];
    const float* enc_ln1 = (const float*)d_in[7];
    const float* enc_w1  = (const float*)d_in[8];
    const float* enc_w2  = (const float*)d_in[9];
    const float* enc_ln2 = (const float*)d_in[10];
    const float* enc_lnf = (const float*)d_in[11];
    const float* dec_sq  = (const float*)d_in[12];
    const float* dec_sk  = (const float*)d_in[13];
    const float* dec_sv  = (const float*)d_in[14];
    const float* dec_so  = (const float*)d_in[15];
    const float* dec_ln1 = (const float*)d_in[16];
    const float* dec_cq  = (const float*)d_in[17];
    const float* dec_ck  = (const float*)d_in[18];
    const float* dec_cv  = (const float*)d_in[19];
    const float* dec_co  = (const float*)d_in[20];
    const float* dec_ln2 = (const float*)d_in[21];
    const float* dec_w1  = (const float*)d_in[22];
    const float* dec_w2  = (const float*)d_in[23];
    const float* dec_ln3 = (const float*)d_in[24];
    const float* dec_lnf = (const float*)d_in[25];
    const float* lm      = (const float*)d_in[26];
    float* out = (float*)d_out;

    float *gx, *gh, *gq, *gk, *gv, *gat, *gff, *ghs, *gckc, *gcvc, *gpart;
    cudaGetSymbolAddress((void**)&gx,   g_x);
    cudaGetSymbolAddress((void**)&gh,   g_h);
    cudaGetSymbolAddress((void**)&gq,   g_q);
    cudaGetSymbolAddress((void**)&gk,   g_k);
    cudaGetSymbolAddress((void**)&gv,   g_v);
    cudaGetSymbolAddress((void**)&gat,  g_at);
    cudaGetSymbolAddress((void**)&gff,  g_ff);
    cudaGetSymbolAddress((void**)&ghs,  g_hs);
    cudaGetSymbolAddress((void**)&gckc, g_ckc);
    cudaGetSymbolAddress((void**)&gcvc, g_cvc);
    cudaGetSymbolAddress((void**)&gpart, g_part);

    const int MROWS = BB*SS;                 // 256
    const size_t DD2 = (size_t)DDIM*DDIM;
    const size_t DF  = (size_t)DDIM*DFF;
    const int MN_DD = MROWS*DDIM;            // 131072
    const int MN_DF = MROWS*DFF;             // 524288

    // D x D GEMM via k-split (4 splits -> 128 blocks) + reduce
    #define GEMM_DD(A, W, RES, C, FLAGS) do {                                          \
        gemm_split<<<dim3(DDIM/64, MROWS/64, 4), 256>>>(A, W, gpart, MROWS, DDIM, DDIM, 4); \
        gemm_reduce<<<MN_DD/1024, 256>>>(gpart, RES, C, MN_DD, 4, FLAGS);              \
    } while (0)

    // ===== encoder =====
    embed_kernel<<<MROWS, 256>>>(ids, emb);
    for (int l = 0; l < LLAY; l++) {
        rmsnorm_kernel<<<MROWS, 256>>>(gx, enc_ln1 + l*DDIM, gh);
        GEMM_DD(gh, enc_wq + l*DD2, nullptr, gq, 0);
        GEMM_DD(gh, enc_wk + l*DD2, nullptr, gk, 0);
        GEMM_DD(gh, enc_wv + l*DD2, nullptr, gv, 0);
        enc_attn<<<BB*HH, 64>>>(gq, gk, gv, mask, gat);
        GEMM_DD(gat, enc_wo + l*DD2, gx, gx, GF_RES);
        rmsnorm_kernel<<<MROWS, 256>>>(gx, enc_ln2 + l*DDIM, gh);
        // W1: [256,512]x[512,2048], k-split 2 -> 256 blocks
        gemm_split<<<dim3(DFF/64, MROWS/64, 2), 256>>>(gh, enc_w1 + l*DF, gpart, MROWS, DFF, DDIM, 2);
        gemm_reduce<<<MN_DF/1024, 256>>>(gpart, nullptr, gff, MN_DF, 2, GF_RELU);
        // W2: [256,2048]x[2048,512], k-split 8 -> 256 blocks
        gemm_split<<<dim3(DDIM/64, MROWS/64, 8), 256>>>(gff, enc_w2 + l*DF, gpart, MROWS, DDIM, DFF, 8);
        gemm_reduce<<<MN_DD/1024, 256>>>(gpart, gx, gx, MN_DD, 8, GF_RES);
    }
    rmsnorm_kernel<<<MROWS, 256>>>(gx, enc_lnf, ghs);

    // cross K/V precompute
    for (int l = 0; l < LLAY; l++) {
        GEMM_DD(ghs, dec_ck + l*DD2, nullptr, gckc + (size_t)l*MROWS*DDIM, 0);
        GEMM_DD(ghs, dec_cv + l*DD2, nullptr, gcvc + (size_t)l*MROWS*DDIM, 0);
    }

    // ===== full 16-iteration decode in ONE persistent kernel =====
    decode_megakernel<<<NB, NT>>>(mask, emb,
                                  dec_sq, dec_sk, dec_sv, dec_so, dec_ln1,
                                  dec_cq, dec_co, dec_ln2,
                                  dec_w1, dec_w2, dec_ln3, dec_lnf,
                                  lm, out);
}

// round 11
// speedup vs baseline: 4.5209x; 2.5545x over previous
#include <cuda_runtime.h>
#include <math.h>

#define BB   4
#define SS   64
#define DDIM 512
#define HH   8
#define DH   64
#define DFF  2048
#define LLAY 2
#define VV   32128
#define TT   16
#define NEGV (-1e9f)

#define GF_RES  1
#define GF_RELU 2

#define NB 148
#define NT 512

// ---------------- scratch (device globals; no allocations) ----------------
__device__ float g_x  [BB*SS*DDIM];
__device__ float g_h  [BB*SS*DDIM];
__device__ float g_q  [BB*SS*DDIM];
__device__ float g_k  [BB*SS*DDIM];
__device__ float g_v  [BB*SS*DDIM];
__device__ float g_at [BB*SS*DDIM];
__device__ float g_ff [BB*SS*DFF];
__device__ float g_hs [BB*SS*DDIM];
__device__ float g_ckc[LLAY*BB*SS*DDIM];
__device__ float g_cvc[LLAY*BB*SS*DDIM];
__device__ float g_skc[LLAY*BB*TT*DDIM];
__device__ float g_svc[LLAY*BB*TT*DDIM];
__device__ float g_xd [BB*DDIM];
__device__ float g_qd [BB*DDIM];
__device__ float g_ad [BB*DDIM];
__device__ float g_fd [BB*DFF];
__device__ float g_logits[BB*VV];
__device__ float g_part[1048576];

__device__ unsigned g_barcnt = 0;
__device__ unsigned g_bargen = 0;

// ======================= encoder kernels =======================
__global__ void embed_kernel(const int* __restrict__ ids, const float* __restrict__ emb) {
    int row = blockIdx.x;
    int id  = ids[row];
    for (int d = threadIdx.x; d < DDIM; d += 256)
        g_x[row*DDIM + d] = emb[(size_t)id*DDIM + d];
}

__global__ void rmsnorm_kernel(const float* __restrict__ x, const float* __restrict__ w,
                               float* __restrict__ o) {
    int r = blockIdx.x, tid = threadIdx.x;
    __shared__ float red[256];
    float a = x[r*DDIM + tid];
    float b = x[r*DDIM + 256 + tid];
    red[tid] = a*a + b*b;
    __syncthreads();
    for (int s = 128; s > 0; s >>= 1) { if (tid < s) red[tid] += red[tid+s]; __syncthreads(); }
    float inv = rsqrtf(red[0] / (float)DDIM + 1e-6f);
    o[r*DDIM + tid]       = a * inv * w[tid];
    o[r*DDIM + 256 + tid] = b * inv * w[256 + tid];
}

__global__ void gemm_split(const float* __restrict__ A, const float* __restrict__ W,
                           float* __restrict__ part, int M, int N, int K, int KS) {
    __shared__ float As[16][64];
    __shared__ float Bs[16][64];
    int row0 = blockIdx.y * 64, col0 = blockIdx.x * 64;
    int ksid = blockIdx.z;
    int kc = K / KS;
    int kbeg = ksid * kc, kend = kbeg + kc;
    int tid = threadIdx.x;
    int ty = tid / 16, tx = tid % 16;
    float acc[4][4];
    #pragma unroll
    for (int i = 0; i < 4; i++)
        #pragma unroll
        for (int j = 0; j < 4; j++) acc[i][j] = 0.f;

    for (int k0 = kbeg; k0 < kend; k0 += 16) {
        #pragma unroll
        for (int p = 0; p < 4; p++) {
            int i = tid + p*256;
            int r = i >> 4, c = i & 15;
            As[c][r] = A[(row0 + r)*K + k0 + c];
        }
        #pragma unroll
        for (int p = 0; p < 4; p++) {
            int i = tid + p*256;
            int r = i >> 6, c = i & 63;
            Bs[r][c] = W[(size_t)(k0 + r)*N + col0 + c];
        }
        __syncthreads();
        #pragma unroll
        for (int k = 0; k < 16; k++) {
            float a[4], b[4];
            #pragma unroll
            for (int i = 0; i < 4; i++) a[i] = As[k][ty*4 + i];
            #pragma unroll
            for (int j = 0; j < 4; j++) b[j] = Bs[k][tx*4 + j];
            #pragma unroll
            for (int i = 0; i < 4; i++)
                #pragma unroll
                for (int j = 0; j < 4; j++) acc[i][j] += a[i]*b[j];
        }
        __syncthreads();
    }
    float* pc = part + (size_t)ksid * M * N;
    #pragma unroll
    for (int i = 0; i < 4; i++) {
        int r = row0 + ty*4 + i;
        #pragma unroll
        for (int j = 0; j < 4; j++)
            pc[(size_t)r*N + col0 + tx*4 + j] = acc[i][j];
    }
}

__global__ void gemm_reduce(const float* __restrict__ part, const float* __restrict__ res,
                            float* __restrict__ C, int MN, int KS, int flags) {
    int i = (blockIdx.x*256 + threadIdx.x) * 4;
    if (i >= MN) return;
    float4 s = *(const float4*)(part + i);
    for (int k = 1; k < KS; k++) {
        float4 p = *(const float4*)(part + (size_t)k*MN + i);
        s.x += p.x; s.y += p.y; s.z += p.z; s.w += p.w;
    }
    if (flags & GF_RES) {
        float4 r = *(const float4*)(res + i);
        s.x += r.x; s.y += r.y; s.z += r.z; s.w += r.w;
    }
    if (flags & GF_RELU) {
        s.x = fmaxf(s.x, 0.f); s.y = fmaxf(s.y, 0.f);
        s.z = fmaxf(s.z, 0.f); s.w = fmaxf(s.w, 0.f);
    }
    *(float4*)(C + i) = s;
}

__global__ void enc_attn(const float* __restrict__ Q, const float* __restrict__ K,
                         const float* __restrict__ V, const float* __restrict__ mask,
                         float* __restrict__ O) {
    int bh = blockIdx.x; int b = bh >> 3, h = bh & 7;
    int tid = threadIdx.x;
    __shared__ float Ks[64*65], Vs[64*65], sc[64], se[64];
    for (int i = tid; i < 4096; i += 64) {
        int r = i >> 6, c = i & 63;
        Ks[r*65 + c] = K[(size_t)(b*SS + r)*DDIM + h*DH + c];
        Vs[r*65 + c] = V[(size_t)(b*SS + r)*DDIM + h*DH + c];
    }
    __syncthreads();
    float bias = (1.f - mask[b*SS + tid]) * NEGV;
    for (int q = 0; q < SS; q++) {
        const float* qr = &Q[(size_t)(b*SS + q)*DDIM + h*DH];
        float s = 0.f;
        #pragma unroll 8
        for (int d = 0; d < DH; d++) s += qr[d]*Ks[tid*65 + d];
        sc[tid] = s * 0.125f + bias;
        __syncthreads();
        float mx = -1e30f;
        for (int j = 0; j < 64; j++) mx = fmaxf(mx, sc[j]);
        se[tid] = expf(sc[tid] - mx);
        __syncthreads();
        float den = 0.f;
        for (int j = 0; j < 64; j++) den += se[j];
        float o = 0.f;
        #pragma unroll 8
        for (int j = 0; j < 64; j++) o += se[j]*Vs[j*65 + tid];
        O[(size_t)(b*SS + q)*DDIM + h*DH + tid] = o / den;
        __syncthreads();
    }
}

// ======================= decode megakernel =======================
__shared__ float  s_xs[4*DFF];     // 32KB   activations [m][k]
__shared__ float4 s_xt[DDIM];      // 8KB    transposed [k] -> (m0,m1,m2,m3)
__shared__ float  s_red[1104];     // 4.4KB
__shared__ float  s_sinv[4];
__shared__ float  s_sc[64];
__shared__ float  s_se[64];

__device__ __forceinline__ void gridbar() {
    __syncthreads();
    if (threadIdx.x == 0) {
        __threadfence();
        unsigned my = *(volatile unsigned*)&g_bargen;
        unsigned a = atomicAdd(&g_barcnt, 1u);
        if (a == gridDim.x - 1) {
            atomicExch(&g_barcnt, 0u);
            __threadfence();
            *(volatile unsigned*)&g_bargen = my + 1u;
        } else {
            while (*(volatile unsigned*)&g_bargen == my) { }
            __threadfence();
        }
    }
    __syncthreads();
}

// K=512 prep: rms stats via shuffle (no atomics); writes s_xs and optional s_xt
__device__ __forceinline__ void prep512(const float* __restrict__ x,
                                        const float* __restrict__ ln, bool xt) {
    int tid = threadIdx.x, lane = tid & 31, w = tid >> 5;
    float v0 = x[tid], v1 = x[512 + tid], v2 = x[1024 + tid], v3 = x[1536 + tid];
    if (ln) {
        float s0 = v0*v0, s1 = v1*v1, s2 = v2*v2, s3 = v3*v3;
        #pragma unroll
        for (int off = 16; off > 0; off >>= 1) {
            s0 += __shfl_xor_sync(0xffffffffu, s0, off);
            s1 += __shfl_xor_sync(0xffffffffu, s1, off);
            s2 += __shfl_xor_sync(0xffffffffu, s2, off);
            s3 += __shfl_xor_sync(0xffffffffu, s3, off);
        }
        if (lane == 0) {
            s_red[w] = s0; s_red[16 + w] = s1; s_red[32 + w] = s2; s_red[48 + w] = s3;
        }
        float lw = ln[tid];
        v0 *= lw; v1 *= lw; v2 *= lw; v3 *= lw;
    }
    s_xs[tid] = v0; s_xs[512 + tid] = v1; s_xs[1024 + tid] = v2; s_xs[1536 + tid] = v3;
    if (xt) s_xt[tid] = make_float4(v0, v1, v2, v3);
    __syncthreads();
    if (ln && tid < 4) {
        float s = 0.f;
        #pragma unroll
        for (int ww = 0; ww < 16; ww++) s += s_red[tid*16 + ww];
        s_sinv[tid] = rsqrtf(s / 512.0f + 1e-6f);
    }
    __syncthreads();
}

// K=2048 relu prep (vectorized, no reduction)
__device__ __forceinline__ void prep_relu2048(const float* __restrict__ x) {
    const float4* xf = (const float4*)x;
    float4* sf = (float4*)s_xs;
    #pragma unroll
    for (int i = threadIdx.x; i < 2048; i += NT) {
        float4 p = xf[i];
        p.x = fmaxf(p.x, 0.f); p.y = fmaxf(p.y, 0.f);
        p.z = fmaxf(p.z, 0.f); p.w = fmaxf(p.w, 0.f);
        sf[i] = p;
    }
    __syncthreads();
}

// block-tile gemv: 16 cols, 32-way k-split, bounded unroll, shfl+smem reduce
template<int K>
__device__ __forceinline__ void gemv_tile(const float* __restrict__ W, int N, int tile,
                                          float* __restrict__ dst, int mstride,
                                          const float* __restrict__ res, int rstride,
                                          bool use_sinv) {
    constexpr int KC = K / 32;
    int tid = threadIdx.x;
    int w = tid >> 5, lane = tid & 31;
    int sub = lane >> 4, c = lane & 15;
    int ks = w*2 + sub;
    int col = tile*16 + c;
    const float* xp = s_xs + ks*KC;
    const float* wp = W + (size_t)(ks*KC)*N + col;
    float a0=0.f, a1=0.f, a2=0.f, a3=0.f;
    for (int k0 = 0; k0 < KC; k0 += 16) {
        #pragma unroll
        for (int k = 0; k < 16; k++) {
            float wv = wp[(size_t)(k0+k)*N];
            a0 += xp[k0+k]*wv; a1 += xp[K+k0+k]*wv;
            a2 += xp[2*K+k0+k]*wv; a3 += xp[3*K+k0+k]*wv;
        }
    }
    a0 += __shfl_xor_sync(0xffffffffu, a0, 16);
    a1 += __shfl_xor_sync(0xffffffffu, a1, 16);
    a2 += __shfl_xor_sync(0xffffffffu, a2, 16);
    a3 += __shfl_xor_sync(0xffffffffu, a3, 16);
    if (sub == 0) {
        s_red[(c*4+0)*17 + w] = a0;
        s_red[(c*4+1)*17 + w] = a1;
        s_red[(c*4+2)*17 + w] = a2;
        s_red[(c*4+3)*17 + w] = a3;
    }
    __syncthreads();
    if (tid < 64) {
        float s = 0.f;
        #pragma unroll
        for (int w2 = 0; w2 < 16; w2++) s += s_red[tid*17 + w2];
        int cc = tid >> 2, m = tid & 3;
        int oc = tile*16 + cc;
        if (use_sinv) s *= s_sinv[m];
        if (res) s += res[(size_t)m*rstride + oc];
        dst[(size_t)m*mstride + oc] = s;
    }
    __syncthreads();
}

template<int K>
__device__ __forceinline__ void gemv_all(const float* __restrict__ W, int N,
                                         float* __restrict__ dst, int mstride,
                                         const float* __restrict__ res, int rstride,
                                         bool use_sinv) {
    int nt = N >> 4;
    for (int t0 = blockIdx.x; t0 < nt; t0 += gridDim.x)
        gemv_tile<K>(W, N, t0, dst, mstride, res, rstride, use_sinv);
}

// warp-per-tile logits: 16 cols/tile, 2-way lane k-split, no block syncs.
// Requires prep512(..., xt=true) done. dst[m*VV+col] = sinv[m] * dot.
__device__ __forceinline__ void logits_warp(const float* __restrict__ lm,
                                            float* __restrict__ dst) {
    int lane = threadIdx.x & 31;
    int gw = blockIdx.x * (NT/32) + (threadIdx.x >> 5);     // global warp id
    float si0 = s_sinv[0], si1 = s_sinv[1], si2 = s_sinv[2], si3 = s_sinv[3];
    int sub = lane >> 4, c = lane & 15;
    const int NTILE = VV / 16;                              // 2008
    for (int tile = gw; tile < NTILE; tile += NB*(NT/32)) {
        int col = tile*16 + c;
        const float4* xp = s_xt + sub*256;
        const float*  wp = lm + (size_t)(sub*256)*VV + col;
        float a0=0.f, a1=0.f, a2=0.f, a3=0.f;
        for (int k0 = 0; k0 < 256; k0 += 16) {
            #pragma unroll
            for (int k = 0; k < 16; k++) {
                float4 x4 = xp[k0+k];
                float wv = wp[(size_t)(k0+k)*VV];
                a0 += x4.x*wv; a1 += x4.y*wv; a2 += x4.z*wv; a3 += x4.w*wv;
            }
        }
        a0 += __shfl_xor_sync(0xffffffffu, a0, 16);
        a1 += __shfl_xor_sync(0xffffffffu, a1, 16);
        a2 += __shfl_xor_sync(0xffffffffu, a2, 16);
        a3 += __shfl_xor_sync(0xffffffffu, a3, 16);
        if (sub == 0) {
            dst[(size_t)0*VV + col] = a0*si0;
            dst[(size_t)1*VV + col] = a1*si1;
            dst[(size_t)2*VV + col] = a2*si2;
            dst[(size_t)3*VV + col] = a3*si3;
        }
    }
}

__global__ void __launch_bounds__(NT, 1)
decode_megakernel(const float* __restrict__ mask, const float* __restrict__ emb,
                  const float* __restrict__ sq, const float* __restrict__ sk,
                  const float* __restrict__ sv, const float* __restrict__ so,
                  const float* __restrict__ ln1, const float* __restrict__ cq,
                  const float* __restrict__ co, const float* __restrict__ ln2,
                  const float* __restrict__ w1, const float* __restrict__ w2,
                  const float* __restrict__ ln3, const float* __restrict__ lnf,
                  const float* __restrict__ lm, float* __restrict__ out) {
    const size_t DD2 = (size_t)DDIM*DDIM;
    const size_t DF  = (size_t)DDIM*DFF;
    int tid = threadIdx.x;

    if (blockIdx.x < 4)
        g_xd[blockIdx.x*DDIM + tid] = emb[tid];
    gridbar();

    for (int t = 0; t < TT; t++) {
        for (int l = 0; l < LLAY; l++) {
            // ---- stage 1: rms(ln1) + QKV ----
            prep512(g_xd, ln1 + l*DDIM, false);
            for (int tt = blockIdx.x; tt < 96; tt += gridDim.x) {
                int seg = tt >> 5, ti = tt & 31;
                if (seg == 0) {
                    gemv_tile<DDIM>(sq + l*DD2, DDIM, ti, g_qd, DDIM, nullptr, 0, true);
                } else if (seg == 1) {
                    gemv_tile<DDIM>(sk + l*DD2, DDIM, ti,
                                    g_skc + (size_t)(l*BB*TT + t)*DDIM, TT*DDIM, nullptr, 0, true);
                } else {
                    gemv_tile<DDIM>(sv + l*DD2, DDIM, ti,
                                    g_svc + (size_t)(l*BB*TT + t)*DDIM, TT*DDIM, nullptr, 0, true);
                }
            }
            gridbar();

            // ---- stage 2: self-attention ----
            if (blockIdx.x < 32) {
                int b = blockIdx.x >> 3, h = blockIdx.x & 7;
                int nk = t + 1;
                const float* q = g_qd + b*DDIM + h*DH;
                if (tid < nk) {
                    const float* kr = g_skc + (size_t)((l*BB + b)*TT + tid)*DDIM + h*DH;
                    float s = 0.f;
                    #pragma unroll 16
                    for (int d = 0; d < DH; d++) s += q[d]*kr[d];
                    s_sc[tid] = s * 0.125f;
                }
                __syncthreads();
                if (tid < nk) {
                    float mx = -1e30f;
                    for (int j = 0; j < nk; j++) mx = fmaxf(mx, s_sc[j]);
                    s_se[tid] = expf(s_sc[tid] - mx);
                }
                __syncthreads();
                if (tid < 64) {
                    float den = 0.f, o = 0.f;
                    for (int j = 0; j < nk; j++) {
                        den += s_se[j];
                        o += s_se[j]*g_svc[(size_t)((l*BB + b)*TT + j)*DDIM + h*DH + tid];
                    }
                    g_ad[b*DDIM + h*DH + tid] = o / den;
                }
            }
            gridbar();

            // ---- stage 3: O-proj + residual ----
            prep512(g_ad, nullptr, false);
            gemv_all<DDIM>(so + l*DD2, DDIM, g_xd, DDIM, g_xd, DDIM, false);
            gridbar();

            // ---- stage 4: rms(ln2) + cross-Q ----
            prep512(g_xd, ln2 + l*DDIM, false);
            gemv_all<DDIM>(cq + l*DD2, DDIM, g_qd, DDIM, nullptr, 0, true);
            gridbar();

            // ---- stage 5: cross-attention ----
            if (blockIdx.x < 32) {
                int b = blockIdx.x >> 3, h = blockIdx.x & 7;
                const float* q = g_qd + b*DDIM + h*DH;
                if (tid < 64) {
                    const float* kr = g_ckc + (size_t)((l*BB + b)*SS + tid)*DDIM + h*DH;
                    float s = 0.f;
                    #pragma unroll 16
                    for (int d = 0; d < DH; d++) s += q[d]*kr[d];
                    s_sc[tid] = s * 0.125f + (1.f - mask[b*SS + tid]) * NEGV;
                }
                __syncthreads();
                if (tid < 64) {
                    float mx = -1e30f;
                    for (int j = 0; j < 64; j++) mx = fmaxf(mx, s_sc[j]);
                    s_se[tid] = expf(s_sc[tid] - mx);
                }
                __syncthreads();
                if (tid < 64) {
                    float den = 0.f, o = 0.f;
                    #pragma unroll 8
                    for (int j = 0; j < 64; j++) {
                        den += s_se[j];
                        o += s_se[j]*g_cvc[(size_t)((l*BB + b)*SS + j)*DDIM + h*DH + tid];
                    }
                    g_ad[b*DDIM + h*DH + tid] = o / den;
                }
            }
            gridbar();

            // ---- stage 6: cross O-proj + residual ----
            prep512(g_ad, nullptr, false);
            gemv_all<DDIM>(co + l*DD2, DDIM, g_xd, DDIM, g_xd, DDIM, false);
            gridbar();

            // ---- stage 7: rms(ln3) + W1 ----
            prep512(g_xd, ln3 + l*DDIM, false);
            gemv_all<DDIM>(w1 + l*DF, DFF, g_fd, DFF, nullptr, 0, true);
            gridbar();

            // ---- stage 8: relu + W2 + residual ----
            prep_relu2048(g_fd);
            gemv_all<DFF>(w2 + l*DF, DDIM, g_xd, DDIM, g_xd, DDIM, false);
            gridbar();
        }

        // ---- logits: warp-per-tile, no intra-stage syncs ----
        prep512(g_xd, lnf, true);
        logits_warp(lm, g_logits);
        gridbar();

        // ---- softmax + argmax + write probs/pred + zero x_dec ----
        if (blockIdx.x < 4) {
            int b = blockIdx.x;
            const float* lg = g_logits + (size_t)b*VV;
            int* sidx = (int*)s_xs;
            float mx = -1e30f; int mi = 0;
            #pragma unroll 4
            for (int v = tid; v < VV; v += NT) {
                float f = lg[v];
                if (f > mx) { mx = f; mi = v; }
            }
            s_red[tid] = mx; sidx[tid] = mi;
            __syncthreads();
            for (int s = 256; s > 0; s >>= 1) {
                if (tid < s) {
                    float o = s_red[tid + s]; int oi = sidx[tid + s];
                    if (o > s_red[tid] || (o == s_red[tid] && oi < sidx[tid])) {
                        s_red[tid] = o; sidx[tid] = oi;
                    }
                }
                __syncthreads();
            }
            float M = s_red[0]; int am = sidx[0];
            __syncthreads();
            float sum = 0.f;
            #pragma unroll 4
            for (int v = tid; v < VV; v += NT) sum += expf(lg[v] - M);
            s_red[tid] = sum;
            __syncthreads();
            for (int s = 256; s > 0; s >>= 1) { if (tid < s) s_red[tid] += s_red[tid + s]; __syncthreads(); }
            float inv = 1.f / s_red[0];
            float* pr = out + (size_t)(b*TT + t)*VV;
            #pragma unroll 4
            for (int v = tid; v < VV; v += NT) pr[v] = expf(lg[v] - M) * inv;
            if (tid == 0)
                out[(size_t)BB*TT*VV + b*TT + t] = (am == 0) ? 1.0f : 0.0f;
            g_xd[b*DDIM + tid] = 0.f;
        }
        gridbar();

        // ---- soft embedding: g_xd += probs @ emb ----
        if (t + 1 < TT) {
            float a0=0.f, a1=0.f, a2=0.f, a3=0.f;
            int d = tid;
            for (int t0 = blockIdx.x; t0 < VV/128; t0 += gridDim.x) {
                int v0 = t0*128;
                __syncthreads();
                {
                    int m = tid >> 7, j = tid & 127;
                    s_red[m*128 + j] = out[(size_t)(m*TT + t)*VV + v0 + j];
                }
                __syncthreads();
                for (int j0 = 0; j0 < 128; j0 += 16) {
                    #pragma unroll
                    for (int j = 0; j < 16; j++) {
                        float e = emb[(size_t)(v0 + j0 + j)*DDIM + d];
                        a0 += s_red[j0+j]*e;     a1 += s_red[128+j0+j]*e;
                        a2 += s_red[256+j0+j]*e; a3 += s_red[384+j0+j]*e;
                    }
                }
            }
            atomicAdd(&g_xd[0*DDIM + d], a0);
            atomicAdd(&g_xd[1*DDIM + d], a1);
            atomicAdd(&g_xd[2*DDIM + d], a2);
            atomicAdd(&g_xd[3*DDIM + d], a3);
            gridbar();
        }
    }
}

// ---------------- launcher ----------------
extern "C" void kernel_launch(void* const* d_in, const int* in_sizes, int n_in,
                              void* d_out, int out_size) {
    const int*   ids     = (const int*)  d_in[0];
    const float* mask    = (const float*)d_in[1];
    const float* emb     = (const float*)d_in[2];
    const float* enc_wq  = (const float*)d_in[3];
    const float* enc_wk  = (const float*)d_in[4];
    const float* enc_wv  = (const float*)d_in[5];
    const float* enc_wo  = (const float*)d_in[6];
    const float* enc_ln1 = (const float*)d_in[7];
    const float* enc_w1  = (const float*)d_in[8];
    const float* enc_w2  = (const float*)d_in[9];
    const float* enc_ln2 = (const float*)d_in[10];
    const float* enc_lnf = (const float*)d_in[11];
    const float* dec_sq  = (const float*)d_in[12];
    const float* dec_sk  = (const float*)d_in[13];
    const float* dec_sv  = (const float*)d_in[14];
    const float* dec_so  = (const float*)d_in[15];
    const float* dec_ln1 = (const float*)d_in[16];
    const float* dec_cq  = (const float*)d_in[17];
    const float* dec_ck  = (const float*)d_in[18];
    const float* dec_cv  = (const float*)d_in[19];
    const float* dec_co  = (const float*)d_in[20];
    const float* dec_ln2 = (const float*)d_in[21];
    const float* dec_w1  = (const float*)d_in[22];
    const float* dec_w2  = (const float*)d_in[23];
    const float* dec_ln3 = (const float*)d_in[24];
    const float* dec_lnf = (const float*)d_in[25];
    const float* lm      = (const float*)d_in[26];
    float* out = (float*)d_out;

    float *gx, *gh, *gq, *gk, *gv, *gat, *gff, *ghs, *gckc, *gcvc, *gpart;
    cudaGetSymbolAddress((void**)&gx,   g_x);
    cudaGetSymbolAddress((void**)&gh,   g_h);
    cudaGetSymbolAddress((void**)&gq,   g_q);
    cudaGetSymbolAddress((void**)&gk,   g_k);
    cudaGetSymbolAddress((void**)&gv,   g_v);
    cudaGetSymbolAddress((void**)&gat,  g_at);
    cudaGetSymbolAddress((void**)&gff,  g_ff);
    cudaGetSymbolAddress((void**)&ghs,  g_hs);
    cudaGetSymbolAddress((void**)&gckc, g_ckc);
    cudaGetSymbolAddress((void**)&gcvc, g_cvc);
    cudaGetSymbolAddress((void**)&gpart, g_part);

    const int MROWS = BB*SS;
    const size_t DD2 = (size_t)DDIM*DDIM;
    const size_t DF  = (size_t)DDIM*DFF;
    const int MN_DD = MROWS*DDIM;
    const int MN_DF = MROWS*DFF;

    #define GEMM_DD(A, W, RES, C, FLAGS) do {                                          \
        gemm_split<<<dim3(DDIM/64, MROWS/64, 4), 256>>>(A, W, gpart, MROWS, DDIM, DDIM, 4); \
        gemm_reduce<<<MN_DD/1024, 256>>>(gpart, RES, C, MN_DD, 4, FLAGS);              \
    } while (0)

    // ===== encoder =====
    embed_kernel<<<MROWS, 256>>>(ids, emb);
    for (int l = 0; l < LLAY; l++) {
        rmsnorm_kernel<<<MROWS, 256>>>(gx, enc_ln1 + l*DDIM, gh);
        GEMM_DD(gh, enc_wq + l*DD2, nullptr, gq, 0);
        GEMM_DD(gh, enc_wk + l*DD2, nullptr, gk, 0);
        GEMM_DD(gh, enc_wv + l*DD2, nullptr, gv, 0);
        enc_attn<<<BB*HH, 64>>>(gq, gk, gv, mask, gat);
        GEMM_DD(gat, enc_wo + l*DD2, gx, gx, GF_RES);
        rmsnorm_kernel<<<MROWS, 256>>>(gx, enc_ln2 + l*DDIM, gh);
        gemm_split<<<dim3(DFF/64, MROWS/64, 2), 256>>>(gh, enc_w1 + l*DF, gpart, MROWS, DFF, DDIM, 2);
        gemm_reduce<<<MN_DF/1024, 256>>>(gpart, nullptr, gff, MN_DF, 2, GF_RELU);
        gemm_split<<<dim3(DDIM/64, MROWS/64, 8), 256>>>(gff, enc_w2 + l*DF, gpart, MROWS, DDIM, DFF, 8);
        gemm_reduce<<<MN_DD/1024, 256>>>(gpart, gx, gx, MN_DD, 8, GF_RES);
    }
    rmsnorm_kernel<<<MROWS, 256>>>(gx, enc_lnf, ghs);

    // cross K/V precompute
    for (int l = 0; l < LLAY; l++) {
        GEMM_DD(ghs, dec_ck + l*DD2, nullptr, gckc + (size_t)l*MROWS*DDIM, 0);
        GEMM_DD(ghs, dec_cv + l*DD2, nullptr, gcvc + (size_t)l*MROWS*DDIM, 0);
    }

    // ===== full 16-iteration decode in ONE persistent kernel =====
    decode_megakernel<<<NB, NT>>>(mask, emb,
                                  dec_sq, dec_sk, dec_sv, dec_so, dec_ln1,
                                  dec_cq, dec_co, dec_ln2,
                                  dec_w1, dec_w2, dec_ln3, dec_lnf,
                                  lm, out);
}